// round 11
// baseline (speedup 1.0000x reference)
#include <cuda_runtime.h>
#include <math.h>

// Problem dims (fixed by the dataset)
#define Bn   4
#define Cn   256
#define HWn  65536
#define Pn   256
#define THRESH_F 0.8f
#define EPSn 1e-5f

typedef unsigned long long ull;

// ---------------------------------------------------------------------------
// Scratch (no cudaMalloc allowed). All mutable state is restored by the
// kernels themselves (or a strictly-later kernel) so graph replays see
// identical initial state.
// ---------------------------------------------------------------------------
__device__ __align__(16) int   g_idx[Bn * Pn];
__device__ __align__(16) float g_feat[Bn * Pn * Cn];   // (B, P, C)
__device__ __align__(16) float g_z[Bn * Pn * Cn];      // (B, P, C)
__device__ __align__(16) float g_z2[Bn * Pn * Cn];     // (B, P, C)

__device__ unsigned int g_hist[3][Bn][65536];    // zero at rest
__device__ unsigned int g_coarse[3][Bn][1024];   // zero at rest
__device__ ull g_prefix[Bn];                     // zero at rest
__device__ int g_K[Bn] = {Pn, Pn, Pn, Pn};       // Pn at rest
__device__ int g_candcnt[Bn];                    // zero at rest
__device__ ull g_cand[Bn][Pn];
__device__ volatile unsigned int g_bar[Bn][8];   // topk barriers (reset by gcn_all)
__device__ volatile unsigned int g_bar2[Bn][2];  // gcn barriers  (reset by scatter)

// ---------------------------------------------------------------------------
// 48-bit composite key: (monotone_float32 << 16) | (0xFFFF - idx)
// ---------------------------------------------------------------------------
__device__ __forceinline__ ull make_key(float e, int i) {
    float v = (e < THRESH_F) ? 0.0f : e;
    unsigned int ub = __float_as_uint(v);
    ub = (ub & 0x80000000u) ? ~ub : (ub | 0x80000000u);
    return ((ull)ub << 16) | (ull)(0xFFFFu - (unsigned int)i);
}

// ---------------------------------------------------------------------------
// SM bulk copy: out <- x (256 MB). SHORT CTAs: 8192 blocks x 256 threads,
// each thread moves 8 float4 (CTA = 32 KB) then exits, so warp slots recycle
// every few microseconds and the high-priority side stream schedules freely.
// ---------------------------------------------------------------------------
__global__ void __launch_bounds__(256)
copy_kernel(const float4* __restrict__ src, float4* __restrict__ dst) {
    const int base = blockIdx.x * 2048 + threadIdx.x;
    #pragma unroll
    for (int j = 0; j < 8; ++j)
        dst[base + j * 256] = src[base + j * 256];
}

// ---------------------------------------------------------------------------
// Per-batch global spin barrier (counter + volatile spin).
// ---------------------------------------------------------------------------
#define NBLK 16
__device__ __forceinline__ void batch_barrier(int b, int slot) {
    __threadfence();
    __syncthreads();
    if (threadIdx.x == 0) {
        atomicAdd((unsigned int*)&g_bar[b][slot], 1u);
        while (g_bar[b][slot] < NBLK) { }
        __threadfence();
    }
    __syncthreads();
}

#define GBLK 32
__device__ __forceinline__ void gcn_barrier(int b, int slot) {
    __threadfence();
    __syncthreads();
    if (threadIdx.x == 0) {
        atomicAdd((unsigned int*)&g_bar2[b][slot], 1u);
        while (g_bar2[b][slot] < GBLK) { }
        __threadfence();
    }
    __syncthreads();
}

// ---------------------------------------------------------------------------
// Whole top-256 in ONE launch. grid = (NBLK, Bn), 1024 threads.
// Keys live in registers across all 3 radix passes + collect.
// ---------------------------------------------------------------------------
__global__ void __launch_bounds__(1024)
topk_all(const float* __restrict__ edge) {
    const int b   = blockIdx.y;
    const int blk = blockIdx.x;
    const int t   = threadIdx.x;
    const int lane = t & 31;
    const int w    = t >> 5;

    const int ibase = blk * 4096 + t * 4;
    const float4 ev = *(const float4*)&edge[(size_t)b * HWn + ibase];
    ull key[4];
    key[0] = make_key(ev.x, ibase + 0);
    key[1] = make_key(ev.y, ibase + 1);
    key[2] = make_key(ev.z, ibase + 2);
    key[3] = make_key(ev.w, ibase + 3);

    __shared__ unsigned int warpsum[32];
    __shared__ unsigned int warpsuf[32];
    __shared__ int sh_chunk;
    __shared__ unsigned int sh_krem;
    __shared__ unsigned int bins[64];
    __shared__ ull skeys[Pn];

    #pragma unroll
    for (int pass = 2; pass >= 0; --pass) {
        const ull pre = (pass == 2) ? 0ull : *(volatile ull*)&g_prefix[b];
        #pragma unroll
        for (int j = 0; j < 4; ++j) {
            const bool active = (pass == 2) ||
                                ((key[j] >> ((pass + 1) * 16)) == pre);
            const unsigned int bin =
                (unsigned int)((key[j] >> (pass * 16)) & 0xFFFFull);
            const unsigned int amask = __ballot_sync(0xFFFFFFFFu, active);
            if (active) {
                unsigned int peers = __match_any_sync(amask, bin);
                if (lane == __ffs(peers) - 1)
                    atomicAdd(&g_hist[pass][b][bin], (unsigned int)__popc(peers));
                unsigned int peersc = __match_any_sync(amask, bin >> 6);
                if (lane == __ffs(peersc) - 1)
                    atomicAdd(&g_coarse[pass][b][bin >> 6], (unsigned int)__popc(peersc));
            }
        }

        batch_barrier(b, pass * 2);

        if (blk == 0) {
            const unsigned int mine = g_coarse[pass][b][t];
            unsigned int suf = mine;
            #pragma unroll
            for (int off = 1; off < 32; off <<= 1) {
                const unsigned int v = __shfl_down_sync(0xFFFFFFFFu, suf, off);
                if (lane + off < 32) suf += v;
            }
            if (lane == 0) warpsum[w] = suf;
            __syncthreads();

            if (w == 0) {
                const unsigned int ws = warpsum[lane];
                unsigned int wsuf = ws;
                #pragma unroll
                for (int off = 1; off < 32; off <<= 1) {
                    const unsigned int v = __shfl_down_sync(0xFFFFFFFFu, wsuf, off);
                    if (lane + off < 32) wsuf += v;
                }
                warpsuf[lane] = wsuf - ws;
            }
            __syncthreads();

            const unsigned int K = (unsigned int)g_K[b];
            const unsigned int suf_t = suf + warpsuf[w];
            const unsigned int above = suf_t - mine;
            if (suf_t >= K && above < K) {
                sh_chunk = t;
                sh_krem = K - above;
            }
            __syncthreads();

            const int chunk = sh_chunk;
            if (t < 64) bins[t] = g_hist[pass][b][chunk * 64 + t];
            __syncthreads();

            if (w == 0) {
                const unsigned int krem = sh_krem;
                const unsigned int lo = bins[lane];
                const unsigned int hi = bins[lane + 32];

                unsigned int suf_hi = hi;
                #pragma unroll
                for (int off = 1; off < 32; off <<= 1) {
                    const unsigned int v = __shfl_down_sync(0xFFFFFFFFu, suf_hi, off);
                    if (lane + off < 32) suf_hi += v;
                }
                const unsigned int hi_total = __shfl_sync(0xFFFFFFFFu, suf_hi, 0);

                unsigned int suf_lo = lo;
                #pragma unroll
                for (int off = 1; off < 32; off <<= 1) {
                    const unsigned int v = __shfl_down_sync(0xFFFFFFFFu, suf_lo, off);
                    if (lane + off < 32) suf_lo += v;
                }
                suf_lo += hi_total;

                { const unsigned int st = suf_hi, ab = st - hi;
                  if (st >= krem && ab < krem) {
                      g_prefix[b] = (g_prefix[b] << 16) | (ull)(chunk * 64 + 32 + lane);
                      g_K[b] = (int)(krem - ab);
                  } }
                { const unsigned int st = suf_lo, ab = st - lo;
                  if (st >= krem && ab < krem) {
                      g_prefix[b] = (g_prefix[b] << 16) | (ull)(chunk * 64 + lane);
                      g_K[b] = (int)(krem - ab);
                  } }
            }
            __syncthreads();
        }

        batch_barrier(b, pass * 2 + 1);
    }

    const ull cutoff = *(volatile ull*)&g_prefix[b];
    #pragma unroll
    for (int j = 0; j < 4; ++j) {
        if (key[j] >= cutoff) {
            const int p = atomicAdd(&g_candcnt[b], 1);
            if (p < Pn) g_cand[b][p] = key[j];
        }
    }

    batch_barrier(b, 6);

    if (blk == 0) {
        if (t < Pn) skeys[t] = g_cand[b][t];
        __syncthreads();
        for (int kk = 2; kk <= Pn; kk <<= 1) {
            for (int jj = kk >> 1; jj > 0; jj >>= 1) {
                if (t < Pn) {
                    const int ixj = t ^ jj;
                    if (ixj > t) {
                        const ull a = skeys[t];
                        const ull c = skeys[ixj];
                        const bool up = ((t & kk) == 0);
                        if (up ? (a < c) : (a > c)) { skeys[t] = c; skeys[ixj] = a; }
                    }
                }
                __syncthreads();
            }
        }
        if (t < Pn)
            g_idx[b * Pn + t] = (int)(0xFFFFu - (unsigned int)(skeys[t] & 0xFFFFull));
        if (t == 0) {
            g_candcnt[b] = 0;
            g_prefix[b] = 0ull;
            g_K[b] = Pn;
        }
    }

    const int gt = blk * 1024 + t;
    #pragma unroll
    for (int p = 0; p < 3; ++p) {
        #pragma unroll
        for (int r = 0; r < 4; ++r)
            g_hist[p][b][gt + r * 16384] = 0u;
        if (gt < 1024) g_coarse[p][b][gt] = 0u;
    }
    // g_bar reset happens in gcn_all (strictly after this kernel).
}

// ---------------------------------------------------------------------------
// Fused gather + GEMM1(+BN+ReLU+res) + GEMM2(+BN+ReLU) in ONE launch.
// grid = (GBLK=32, Bn) = 128 CTAs, 512 threads (16 warps -> 4/SMSP).
// CTA (blk): iy = blk>>2 selects 32-row group, dx = blk&3 selects 64-col group.
// Per-batch spin barriers between stages (all 128 CTAs co-resident).
// ---------------------------------------------------------------------------
__global__ void __launch_bounds__(512)
gcn_all(const float* __restrict__ x,
        const float* __restrict__ W,
        const float* __restrict__ ga, const float* __restrict__ ba,
        const float* __restrict__ ma, const float* __restrict__ va,
        const float* __restrict__ Wg,
        const float* __restrict__ gw, const float* __restrict__ bw,
        const float* __restrict__ mw, const float* __restrict__ vw) {
    __shared__ __align__(16) float sA[32][33];   // [k][row]  32x32 + pad
    __shared__ __align__(16) float sB[32][68];   // [k][col]  32x64 + pad

    const int b   = blockIdx.y;
    const int blk = blockIdx.x;
    const int t   = threadIdx.x;
    const int iy  = blk >> 2;     // 0..7
    const int dx  = blk & 3;      // 0..3
    const int ti  = iy * 32;
    const int td  = dx * 64;
    const int ty  = t >> 4;       // 0..31 (row)
    const int tx  = t & 15;       // 0..15 (4-col group)

    float* F = g_feat + b * Pn * Cn;
    float* Z = g_z    + b * Pn * Cn;
    float* Z2 = g_z2  + b * Pn * Cn;

    // Reset topk barrier counters (topk_all strictly precedes this kernel).
    if (blk == 0 && t < 8) g_bar[b][t] = 0u;

    // ---- stage 0: gather. CTA handles n-rows [blk*8, blk*8+8). ----
    {
        const int n  = blk * 8 + (t >> 6);
        const int d0 = (t & 63) * 4;
        const int col = g_idx[b * Pn + n];
        const float* xp = x + (size_t)b * Cn * HWn + col;
        float4 v;
        v.x = xp[(size_t)(d0 + 0) * HWn];
        v.y = xp[(size_t)(d0 + 1) * HWn];
        v.z = xp[(size_t)(d0 + 2) * HWn];
        v.w = xp[(size_t)(d0 + 3) * HWn];
        *(float4*)&F[n * Cn + d0] = v;
    }
    gcn_barrier(b, 0);

    // ---- stage 1: GEMM1 tile: Z[i,d] = relu(BN(sum_j W[i,j]F[j,d])) + F[i,d]
    {
        float acc[4] = {};
        for (int k0 = 0; k0 < Pn; k0 += 32) {
            #pragma unroll
            for (int r = 0; r < 2; ++r) {               // A: 32x32
                const int eI = t + r * 512;
                const int ai = eI >> 5, ak = eI & 31;
                sA[ak][ai] = W[(ti + ai) * Pn + (k0 + ak)];
            }
            #pragma unroll
            for (int r = 0; r < 4; ++r) {               // B: 32x64
                const int eI = t + r * 512;
                const int bk = eI >> 6, bd = eI & 63;
                sB[bk][bd] = F[(k0 + bk) * Cn + (td + bd)];
            }
            __syncthreads();
            #pragma unroll
            for (int k = 0; k < 32; ++k) {
                const float a = sA[k][ty];
                const float4 b4 = *(const float4*)&sB[k][tx * 4];
                acc[0] += a * b4.x;
                acc[1] += a * b4.y;
                acc[2] += a * b4.z;
                acc[3] += a * b4.w;
            }
            __syncthreads();
        }
        const int i = ti + ty;
        const float inv = ga[i] * rsqrtf(va[i] + EPSn);
        const float add = ba[i] - ma[i] * inv;
        const int d = td + tx * 4;
        const float4 f4 = *(const float4*)&F[i * Cn + d];
        float4 o;
        o.x = fmaxf(acc[0] * inv + add, 0.0f) + f4.x;
        o.y = fmaxf(acc[1] * inv + add, 0.0f) + f4.y;
        o.z = fmaxf(acc[2] * inv + add, 0.0f) + f4.z;
        o.w = fmaxf(acc[3] * inv + add, 0.0f) + f4.w;
        *(float4*)&Z[i * Cn + d] = o;
    }
    gcn_barrier(b, 1);

    // ---- stage 2: GEMM2 tile: z2[p,c] = relu(BN(sum_k Z[p,k]Wg[c,k])) ----
    {
        float acc[4] = {};
        for (int k0 = 0; k0 < Cn; k0 += 32) {
            #pragma unroll
            for (int r = 0; r < 2; ++r) {               // A: Z 32 rows x 32 k
                const int eI = t + r * 512;
                const int ar = eI >> 5, ak = eI & 31;
                sA[ak][ar] = Z[(ti + ar) * Cn + (k0 + ak)];
            }
            #pragma unroll
            for (int r = 0; r < 4; ++r) {               // B: Wg 64 rows x 32 k
                const int eI = t + r * 512;
                const int br = eI >> 5, bk = eI & 31;
                sB[bk][br] = Wg[(td + br) * Cn + (k0 + bk)];
            }
            __syncthreads();
            #pragma unroll
            for (int k = 0; k < 32; ++k) {
                const float a = sA[k][ty];
                const float4 b4 = *(const float4*)&sB[k][tx * 4];
                acc[0] += a * b4.x;
                acc[1] += a * b4.y;
                acc[2] += a * b4.z;
                acc[3] += a * b4.w;
            }
            __syncthreads();
        }
        const int p = ti + ty;
        #pragma unroll
        for (int j = 0; j < 4; ++j) {
            const int c = td + tx * 4 + j;
            const float inv = gw[c] * rsqrtf(vw[c] + EPSn);
            const float add = bw[c] - mw[c] * inv;
            Z2[p * Cn + c] = fmaxf(acc[j] * inv + add, 0.0f);
        }
    }
    // g_bar2 reset happens in scatter_kernel (strictly after this kernel).
}

// ---------------------------------------------------------------------------
// Scatter: out[b, c, idx[b,p]] = z2[b,p,c].  grid (Pn, Bn), 256 threads (c).
// Also resets gcn barrier counters for the next graph replay.
// ---------------------------------------------------------------------------
__global__ void __launch_bounds__(256)
scatter_kernel(float* __restrict__ out) {
    const int b = blockIdx.y;
    const int p = blockIdx.x;
    const int c = threadIdx.x;
    if (p == 0 && c < 2) g_bar2[b][c] = 0u;
    const int col = g_idx[b * Pn + p];
    out[(size_t)b * Cn * HWn + (size_t)c * HWn + (size_t)col] =
        g_z2[((b * Pn + p) << 8) + c];
}

// ---------------------------------------------------------------------------
extern "C" void kernel_launch(void* const* d_in, const int* in_sizes, int n_in,
                              void* d_out, int out_size) {
    const float* x     = (const float*)d_in[0];
    const float* edge  = (const float*)d_in[1];
    const float* w_adj = (const float*)d_in[2];
    const float* g_adj = (const float*)d_in[3];
    const float* b_adj = (const float*)d_in[4];
    const float* m_adj = (const float*)d_in[5];
    const float* v_adj = (const float*)d_in[6];
    const float* w_wg  = (const float*)d_in[7];
    const float* g_wg  = (const float*)d_in[8];
    const float* b_wg  = (const float*)d_in[9];
    const float* m_wg  = (const float*)d_in[10];
    const float* v_wg  = (const float*)d_in[11];
    float* out = (float*)d_out;

    static cudaStream_t s1 = nullptr;
    static cudaEvent_t evA = nullptr, evB = nullptr;
    if (s1 == nullptr) {
        int lo = 0, hi = 0;
        cudaDeviceGetStreamPriorityRange(&lo, &hi);   // hi = greatest priority
        cudaStreamCreateWithPriority(&s1, cudaStreamNonBlocking, hi);
        cudaEventCreateWithFlags(&evA, cudaEventDisableTiming);
        cudaEventCreateWithFlags(&evB, cudaEventDisableTiming);
    }

    // Fork side stream from stream 0.
    cudaEventRecord(evA, 0);
    cudaStreamWaitEvent(s1, evA, 0);

    // High-priority side stream: topk -> fused gather+GCN.
    topk_all<<<dim3(NBLK, Bn), 1024, 0, s1>>>(edge);
    gcn_all<<<dim3(GBLK, Bn), 512, 0, s1>>>(x, w_adj, g_adj, b_adj, m_adj, v_adj,
                                            w_wg, g_wg, b_wg, m_wg, v_wg);

    // Stream 0: bulk copy x -> out (short CTAs; slots recycle continuously).
    copy_kernel<<<8192, 256>>>((const float4*)x, (float4*)out);

    // Join and scatter the reasoned point features into out.
    cudaEventRecord(evB, s1);
    cudaStreamWaitEvent(0, evB, 0);
    scatter_kernel<<<dim3(Pn, Bn), 256>>>(out);
}

// round 12
// speedup vs baseline: 1.2566x; 1.2566x over previous
#include <cuda_runtime.h>
#include <math.h>

// Problem dims (fixed by the dataset)
#define Bn   4
#define Cn   256
#define HWn  65536
#define Pn   256
#define THRESH_F 0.8f
#define EPSn 1e-5f

typedef unsigned long long ull;

// ---------------------------------------------------------------------------
// Scratch (no cudaMalloc allowed). All mutable state is restored by the
// kernels themselves (or a strictly-later kernel) so graph replays see
// identical initial state.
// ---------------------------------------------------------------------------
__device__ __align__(16) int   g_idx[Bn * Pn];
__device__ __align__(16) float g_feat[Bn * Pn * Cn];   // (B, P, C)
__device__ __align__(16) float g_z[Bn * Pn * Cn];      // (B, P, C)
__device__ __align__(16) float g_z2[Bn * Pn * Cn];     // (B, P, C)

__device__ unsigned int g_hist[3][Bn][65536];    // zero at rest
__device__ unsigned int g_coarse[3][Bn][1024];   // zero at rest
__device__ ull g_prefix[Bn];                     // zero at rest
__device__ int g_K[Bn] = {Pn, Pn, Pn, Pn};       // Pn at rest
__device__ int g_candcnt[Bn];                    // zero at rest
__device__ ull g_cand[Bn][Pn];
__device__ volatile unsigned int g_bar[Bn][8];   // zero at rest (reset by gather)

// ---------------------------------------------------------------------------
// 48-bit composite key: (monotone_float32 << 16) | (0xFFFF - idx)
// ---------------------------------------------------------------------------
__device__ __forceinline__ ull make_key(float e, int i) {
    float v = (e < THRESH_F) ? 0.0f : e;
    unsigned int ub = __float_as_uint(v);
    ub = (ub & 0x80000000u) ? ~ub : (ub | 0x80000000u);
    return ((ull)ub << 16) | (ull)(0xFFFFu - (unsigned int)i);
}

// ---------------------------------------------------------------------------
// SM bulk copy: out <- x  (256 MB). float4 grid-stride, 512 CTAs
// (proven round-10 configuration).
// ---------------------------------------------------------------------------
__global__ void __launch_bounds__(256)
copy_kernel(const float4* __restrict__ src, float4* __restrict__ dst) {
    const int n4 = Bn * Cn * HWn / 4;
    int i = blockIdx.x * blockDim.x + threadIdx.x;
    const int stride = gridDim.x * blockDim.x;
    #pragma unroll 4
    for (; i < n4; i += stride) dst[i] = src[i];
}

// ---------------------------------------------------------------------------
// Per-batch global barrier over NBLK blocks (counter + volatile spin).
// ---------------------------------------------------------------------------
#define NBLK 16
__device__ __forceinline__ void batch_barrier(int b, int slot) {
    __threadfence();
    __syncthreads();
    if (threadIdx.x == 0) {
        atomicAdd((unsigned int*)&g_bar[b][slot], 1u);
        while (g_bar[b][slot] < NBLK) { }
        __threadfence();
    }
    __syncthreads();
}

// ---------------------------------------------------------------------------
// Whole top-256 in ONE launch. grid = (NBLK, Bn), 1024 threads.
// ---------------------------------------------------------------------------
__global__ void __launch_bounds__(1024)
topk_all(const float* __restrict__ edge) {
    const int b   = blockIdx.y;
    const int blk = blockIdx.x;
    const int t   = threadIdx.x;
    const int lane = t & 31;
    const int w    = t >> 5;

    const int ibase = blk * 4096 + t * 4;
    const float4 ev = *(const float4*)&edge[(size_t)b * HWn + ibase];
    ull key[4];
    key[0] = make_key(ev.x, ibase + 0);
    key[1] = make_key(ev.y, ibase + 1);
    key[2] = make_key(ev.z, ibase + 2);
    key[3] = make_key(ev.w, ibase + 3);

    __shared__ unsigned int warpsum[32];
    __shared__ unsigned int warpsuf[32];
    __shared__ int sh_chunk;
    __shared__ unsigned int sh_krem;
    __shared__ unsigned int bins[64];
    __shared__ ull skeys[Pn];

    #pragma unroll
    for (int pass = 2; pass >= 0; --pass) {
        const ull pre = (pass == 2) ? 0ull : *(volatile ull*)&g_prefix[b];
        #pragma unroll
        for (int j = 0; j < 4; ++j) {
            const bool active = (pass == 2) ||
                                ((key[j] >> ((pass + 1) * 16)) == pre);
            const unsigned int bin =
                (unsigned int)((key[j] >> (pass * 16)) & 0xFFFFull);
            const unsigned int amask = __ballot_sync(0xFFFFFFFFu, active);
            if (active) {
                unsigned int peers = __match_any_sync(amask, bin);
                if (lane == __ffs(peers) - 1)
                    atomicAdd(&g_hist[pass][b][bin], (unsigned int)__popc(peers));
                unsigned int peersc = __match_any_sync(amask, bin >> 6);
                if (lane == __ffs(peersc) - 1)
                    atomicAdd(&g_coarse[pass][b][bin >> 6], (unsigned int)__popc(peersc));
            }
        }

        batch_barrier(b, pass * 2);

        if (blk == 0) {
            const unsigned int mine = g_coarse[pass][b][t];
            unsigned int suf = mine;
            #pragma unroll
            for (int off = 1; off < 32; off <<= 1) {
                const unsigned int v = __shfl_down_sync(0xFFFFFFFFu, suf, off);
                if (lane + off < 32) suf += v;
            }
            if (lane == 0) warpsum[w] = suf;
            __syncthreads();

            if (w == 0) {
                const unsigned int ws = warpsum[lane];
                unsigned int wsuf = ws;
                #pragma unroll
                for (int off = 1; off < 32; off <<= 1) {
                    const unsigned int v = __shfl_down_sync(0xFFFFFFFFu, wsuf, off);
                    if (lane + off < 32) wsuf += v;
                }
                warpsuf[lane] = wsuf - ws;
            }
            __syncthreads();

            const unsigned int K = (unsigned int)g_K[b];
            const unsigned int suf_t = suf + warpsuf[w];
            const unsigned int above = suf_t - mine;
            if (suf_t >= K && above < K) {
                sh_chunk = t;
                sh_krem = K - above;
            }
            __syncthreads();

            const int chunk = sh_chunk;
            if (t < 64) bins[t] = g_hist[pass][b][chunk * 64 + t];
            __syncthreads();

            if (w == 0) {
                const unsigned int krem = sh_krem;
                const unsigned int lo = bins[lane];
                const unsigned int hi = bins[lane + 32];

                unsigned int suf_hi = hi;
                #pragma unroll
                for (int off = 1; off < 32; off <<= 1) {
                    const unsigned int v = __shfl_down_sync(0xFFFFFFFFu, suf_hi, off);
                    if (lane + off < 32) suf_hi += v;
                }
                const unsigned int hi_total = __shfl_sync(0xFFFFFFFFu, suf_hi, 0);

                unsigned int suf_lo = lo;
                #pragma unroll
                for (int off = 1; off < 32; off <<= 1) {
                    const unsigned int v = __shfl_down_sync(0xFFFFFFFFu, suf_lo, off);
                    if (lane + off < 32) suf_lo += v;
                }
                suf_lo += hi_total;

                { const unsigned int st = suf_hi, ab = st - hi;
                  if (st >= krem && ab < krem) {
                      g_prefix[b] = (g_prefix[b] << 16) | (ull)(chunk * 64 + 32 + lane);
                      g_K[b] = (int)(krem - ab);
                  } }
                { const unsigned int st = suf_lo, ab = st - lo;
                  if (st >= krem && ab < krem) {
                      g_prefix[b] = (g_prefix[b] << 16) | (ull)(chunk * 64 + lane);
                      g_K[b] = (int)(krem - ab);
                  } }
            }
            __syncthreads();
        }

        batch_barrier(b, pass * 2 + 1);
    }

    const ull cutoff = *(volatile ull*)&g_prefix[b];
    #pragma unroll
    for (int j = 0; j < 4; ++j) {
        if (key[j] >= cutoff) {
            const int p = atomicAdd(&g_candcnt[b], 1);
            if (p < Pn) g_cand[b][p] = key[j];
        }
    }

    batch_barrier(b, 6);

    if (blk == 0) {
        if (t < Pn) skeys[t] = g_cand[b][t];
        __syncthreads();
        for (int kk = 2; kk <= Pn; kk <<= 1) {
            for (int jj = kk >> 1; jj > 0; jj >>= 1) {
                if (t < Pn) {
                    const int ixj = t ^ jj;
                    if (ixj > t) {
                        const ull a = skeys[t];
                        const ull c = skeys[ixj];
                        const bool up = ((t & kk) == 0);
                        if (up ? (a < c) : (a > c)) { skeys[t] = c; skeys[ixj] = a; }
                    }
                }
                __syncthreads();
            }
        }
        if (t < Pn)
            g_idx[b * Pn + t] = (int)(0xFFFFu - (unsigned int)(skeys[t] & 0xFFFFull));
        if (t == 0) {
            g_candcnt[b] = 0;
            g_prefix[b] = 0ull;
            g_K[b] = Pn;
        }
    }

    const int gt = blk * 1024 + t;
    #pragma unroll
    for (int p = 0; p < 3; ++p) {
        #pragma unroll
        for (int r = 0; r < 4; ++r)
            g_hist[p][b][gt + r * 16384] = 0u;
        if (gt < 1024) g_coarse[p][b][gt] = 0u;
    }
    // g_bar reset happens in gather_kernel (strictly after this kernel).
}

// ---------------------------------------------------------------------------
// Gather: feat[b][n][d] = x[b][d][idx[b][n]]   grid (Pn, Bn), 256 threads (d)
// Also resets topk barrier counters for the next graph replay.
// ---------------------------------------------------------------------------
__global__ void gather_kernel(const float* __restrict__ x) {
    const int b = blockIdx.y;
    const int n = blockIdx.x;
    const int d = threadIdx.x;
    if (n == 0 && d < 8) g_bar[b][d] = 0u;
    const int col = g_idx[b * Pn + n];
    g_feat[((b * Pn + n) << 8) + d] =
        x[(size_t)b * Cn * HWn + (size_t)d * HWn + (size_t)col];
}

// ---------------------------------------------------------------------------
// GEMM1 (NN), double-buffered, 512 threads, 64x64 tile, KB=32.
// Z[i,d] = relu(BN(sum_j W[i,j]*F[j,d])) + F[i,d]
// grid = (4 d-tiles, 4 i-tiles, Bn) = 64 CTAs, 16 warps/CTA (4/SMSP).
// ---------------------------------------------------------------------------
__global__ void __launch_bounds__(512)
gemm1_kernel(const float* __restrict__ W,
             const float* __restrict__ ga, const float* __restrict__ ba,
             const float* __restrict__ ma, const float* __restrict__ va) {
    __shared__ __align__(16) float sA[2][32][65];   // [stage][k][i] (conflict-free stores)
    __shared__ __align__(16) float sB[2][32][68];   // [stage][k][d] (16B-aligned rows)

    const int b  = blockIdx.z;
    const float* F = g_feat + b * Pn * Cn;
    float* Z       = g_z    + b * Pn * Cn;
    const int ti = blockIdx.y * 64;
    const int td = blockIdx.x * 64;
    const int t  = threadIdx.x;
    const int tx = t & 15;        // 4 cols
    const int ty = t >> 4;        // 0..31 -> 2 rows

    // A: 64x32 tile, 512 float4 -> 1/thread. ai=row, ak=k-offset.
    const int ai = t >> 3, ak = (t & 7) * 4;
    // B: 32x64 tile, 512 float4 -> 1/thread.
    const int bk = t >> 4, bd = (t & 15) * 4;

    float4 na, nb;
    float acc[2][4] = {};

    na = *(const float4*)&W[(ti + ai) * Pn + ak];
    nb = *(const float4*)&F[bk * Cn + td + bd];
    sA[0][ak + 0][ai] = na.x; sA[0][ak + 1][ai] = na.y;
    sA[0][ak + 2][ai] = na.z; sA[0][ak + 3][ai] = na.w;
    *(float4*)&sB[0][bk][bd] = nb;
    __syncthreads();

    #pragma unroll
    for (int kt = 0; kt < 8; ++kt) {
        const int st = kt & 1;
        if (kt < 7) {
            const int k0 = (kt + 1) * 32;
            na = *(const float4*)&W[(ti + ai) * Pn + k0 + ak];
            nb = *(const float4*)&F[(k0 + bk) * Cn + td + bd];
        }
        #pragma unroll
        for (int k = 0; k < 32; ++k) {
            const float a0 = sA[st][k][ty * 2 + 0];
            const float a1 = sA[st][k][ty * 2 + 1];
            const float4 b4 = *(const float4*)&sB[st][k][tx * 4];
            acc[0][0] += a0 * b4.x; acc[0][1] += a0 * b4.y;
            acc[0][2] += a0 * b4.z; acc[0][3] += a0 * b4.w;
            acc[1][0] += a1 * b4.x; acc[1][1] += a1 * b4.y;
            acc[1][2] += a1 * b4.z; acc[1][3] += a1 * b4.w;
        }
        if (kt < 7) {
            const int sn = st ^ 1;
            sA[sn][ak + 0][ai] = na.x; sA[sn][ak + 1][ai] = na.y;
            sA[sn][ak + 2][ai] = na.z; sA[sn][ak + 3][ai] = na.w;
            *(float4*)&sB[sn][bk][bd] = nb;
        }
        __syncthreads();
    }

    const int d = td + tx * 4;
    #pragma unroll
    for (int ui = 0; ui < 2; ++ui) {
        const int i = ti + ty * 2 + ui;
        const float inv = ga[i] * rsqrtf(va[i] + EPSn);
        const float add = ba[i] - ma[i] * inv;
        const float4 f4 = *(const float4*)&F[i * Cn + d];
        float4 o;
        o.x = fmaxf(acc[ui][0] * inv + add, 0.0f) + f4.x;
        o.y = fmaxf(acc[ui][1] * inv + add, 0.0f) + f4.y;
        o.z = fmaxf(acc[ui][2] * inv + add, 0.0f) + f4.z;
        o.w = fmaxf(acc[ui][3] * inv + add, 0.0f) + f4.w;
        *(float4*)&Z[i * Cn + d] = o;
    }
}

// ---------------------------------------------------------------------------
// GEMM2 (NT), double-buffered, 512 threads, 64(p)x64(c) tile, KB=32.
// z2[p,c] = relu(BN(sum_k Z[p,k]*Wg[c,k]))
// grid = (4 c-tiles, 4 p-tiles, Bn) = 64 CTAs.
// ---------------------------------------------------------------------------
__global__ void __launch_bounds__(512)
gemm2_kernel(const float* __restrict__ Wg,
             const float* __restrict__ gw, const float* __restrict__ bw,
             const float* __restrict__ mw, const float* __restrict__ vw) {
    __shared__ __align__(16) float sA[2][32][65];   // [stage][k][p]
    __shared__ __align__(16) float sB[2][32][68];   // [stage][k][c]

    const int b = blockIdx.z;
    const float* Z = g_z  + b * Pn * Cn;
    float* Z2      = g_z2 + b * Pn * Cn;
    const int tp = blockIdx.y * 64;
    const int tc = blockIdx.x * 64;
    const int t  = threadIdx.x;
    const int tx = t & 15;
    const int ty = t >> 4;

    // Both A and B are k-major 64-row x 32-k tiles: 512 float4 -> 1/thread.
    const int ar = t >> 3, ak = (t & 7) * 4;

    float4 na, nb;
    float acc[2][4] = {};

    na = *(const float4*)&Z[(tp + ar) * Cn + ak];
    nb = *(const float4*)&Wg[(tc + ar) * Cn + ak];
    sA[0][ak + 0][ar] = na.x; sA[0][ak + 1][ar] = na.y;
    sA[0][ak + 2][ar] = na.z; sA[0][ak + 3][ar] = na.w;
    sB[0][ak + 0][ar] = nb.x; sB[0][ak + 1][ar] = nb.y;
    sB[0][ak + 2][ar] = nb.z; sB[0][ak + 3][ar] = nb.w;
    __syncthreads();

    #pragma unroll
    for (int kt = 0; kt < 8; ++kt) {
        const int st = kt & 1;
        if (kt < 7) {
            const int k0 = (kt + 1) * 32;
            na = *(const float4*)&Z[(tp + ar) * Cn + k0 + ak];
            nb = *(const float4*)&Wg[(tc + ar) * Cn + k0 + ak];
        }
        #pragma unroll
        for (int k = 0; k < 32; ++k) {
            const float a0 = sA[st][k][ty * 2 + 0];
            const float a1 = sA[st][k][ty * 2 + 1];
            const float4 b4 = *(const float4*)&sB[st][k][tx * 4];
            acc[0][0] += a0 * b4.x; acc[0][1] += a0 * b4.y;
            acc[0][2] += a0 * b4.z; acc[0][3] += a0 * b4.w;
            acc[1][0] += a1 * b4.x; acc[1][1] += a1 * b4.y;
            acc[1][2] += a1 * b4.z; acc[1][3] += a1 * b4.w;
        }
        if (kt < 7) {
            const int sn = st ^ 1;
            sA[sn][ak + 0][ar] = na.x; sA[sn][ak + 1][ar] = na.y;
            sA[sn][ak + 2][ar] = na.z; sA[sn][ak + 3][ar] = na.w;
            sB[sn][ak + 0][ar] = nb.x; sB[sn][ak + 1][ar] = nb.y;
            sB[sn][ak + 2][ar] = nb.z; sB[sn][ak + 3][ar] = nb.w;
        }
        __syncthreads();
    }

    #pragma unroll
    for (int uc = 0; uc < 4; ++uc) {
        const int c = tc + tx * 4 + uc;
        const float inv = gw[c] * rsqrtf(vw[c] + EPSn);
        const float add = bw[c] - mw[c] * inv;
        #pragma unroll
        for (int ui = 0; ui < 2; ++ui) {
            const int p = tp + ty * 2 + ui;
            Z2[p * Cn + c] = fmaxf(acc[ui][uc] * inv + add, 0.0f);
        }
    }
}

// ---------------------------------------------------------------------------
// Scatter: out[b, c, idx[b,p]] = z2[b,p,c].  grid (Pn, Bn), 256 threads (c).
// ---------------------------------------------------------------------------
__global__ void __launch_bounds__(256)
scatter_kernel(float* __restrict__ out) {
    const int b = blockIdx.y;
    const int p = blockIdx.x;
    const int c = threadIdx.x;
    const int col = g_idx[b * Pn + p];
    out[(size_t)b * Cn * HWn + (size_t)c * HWn + (size_t)col] =
        g_z2[((b * Pn + p) << 8) + c];
}

// ---------------------------------------------------------------------------
extern "C" void kernel_launch(void* const* d_in, const int* in_sizes, int n_in,
                              void* d_out, int out_size) {
    const float* x     = (const float*)d_in[0];
    const float* edge  = (const float*)d_in[1];
    const float* w_adj = (const float*)d_in[2];
    const float* g_adj = (const float*)d_in[3];
    const float* b_adj = (const float*)d_in[4];
    const float* m_adj = (const float*)d_in[5];
    const float* v_adj = (const float*)d_in[6];
    const float* w_wg  = (const float*)d_in[7];
    const float* g_wg  = (const float*)d_in[8];
    const float* b_wg  = (const float*)d_in[9];
    const float* m_wg  = (const float*)d_in[10];
    const float* v_wg  = (const float*)d_in[11];
    float* out = (float*)d_out;

    static cudaStream_t s1 = nullptr;
    static cudaEvent_t evA = nullptr, evB = nullptr;
    if (s1 == nullptr) {
        int lo = 0, hi = 0;
        cudaDeviceGetStreamPriorityRange(&lo, &hi);   // hi = greatest priority
        cudaStreamCreateWithPriority(&s1, cudaStreamNonBlocking, hi);
        cudaEventCreateWithFlags(&evA, cudaEventDisableTiming);
        cudaEventCreateWithFlags(&evB, cudaEventDisableTiming);
    }

    // Fork side stream from stream 0.
    cudaEventRecord(evA, 0);
    cudaStreamWaitEvent(s1, evA, 0);

    // High-priority side stream first: topk -> gather -> GEMMs.
    topk_all<<<dim3(NBLK, Bn), 1024, 0, s1>>>(edge);
    gather_kernel<<<dim3(Pn, Bn), Cn, 0, s1>>>(x);
    gemm1_kernel<<<dim3(4, 4, Bn), 512, 0, s1>>>(w_adj, g_adj, b_adj, m_adj, v_adj);
    gemm2_kernel<<<dim3(4, 4, Bn), 512, 0, s1>>>(w_wg, g_wg, b_wg, m_wg, v_wg);

    // Stream 0: bulk copy x -> out on the SMs (512 CTAs: leaves residency).
    copy_kernel<<<512, 256>>>((const float4*)x, (float4*)out);

    // Join and scatter the reasoned point features into out.
    cudaEventRecord(evB, s1);
    cudaStreamWaitEvent(0, evB, 0);
    scatter_kernel<<<dim3(Pn, Bn), 256>>>(out);
}

// round 13
// speedup vs baseline: 1.2847x; 1.0224x over previous
#include <cuda_runtime.h>
#include <math.h>

// Problem dims (fixed by the dataset)
#define Bn   4
#define Cn   256
#define HWn  65536
#define Pn   256
#define THRESH_F 0.8f
#define EPSn 1e-5f

typedef unsigned long long ull;

// ---------------------------------------------------------------------------
// Scratch (no cudaMalloc). All state restored for graph replay:
// hist/coarse/prefix/K/candcnt reset inside mega; g_bar reset by scatter.
// ---------------------------------------------------------------------------
__device__ __align__(16) int   g_idx[Bn * Pn];
__device__ __align__(16) float g_feat[Bn * Pn * Cn];   // (B, P, C)
__device__ __align__(16) float g_z[Bn * Pn * Cn];      // (B, P, C)
__device__ __align__(16) float g_z2[Bn * Pn * Cn];     // (B, P, C)

__device__ unsigned int g_hist[3][Bn][65536];    // zero at rest
__device__ unsigned int g_coarse[3][Bn][1024];   // zero at rest
__device__ ull g_prefix[Bn];                     // zero at rest
__device__ int g_K[Bn] = {Pn, Pn, Pn, Pn};       // Pn at rest
__device__ int g_candcnt[Bn];                    // zero at rest
__device__ ull g_cand[Bn][Pn];
__device__ volatile unsigned int g_bar[Bn][12];  // zero at rest (reset by scatter)

#define NSIDE 64            // 16 CTAs per batch
#define NCOPY 224
#define NTOT  (NSIDE + NCOPY)   // 288 <= 296 co-resident (512thr, <=64 regs)
#define NBLK  16            // side CTAs per batch

// ---------------------------------------------------------------------------
// 48-bit composite key: (monotone_float32 << 16) | (0xFFFF - idx)
// ---------------------------------------------------------------------------
__device__ __forceinline__ ull make_key(float e, int i) {
    float v = (e < THRESH_F) ? 0.0f : e;
    unsigned int ub = __float_as_uint(v);
    ub = (ub & 0x80000000u) ? ~ub : (ub | 0x80000000u);
    return ((ull)ub << 16) | (ull)(0xFFFFu - (unsigned int)i);
}

// Per-batch spin barrier over the NBLK side CTAs of batch b.
__device__ __forceinline__ void batch_barrier(int b, int slot) {
    __threadfence();
    __syncthreads();
    if (threadIdx.x == 0) {
        atomicAdd((unsigned int*)&g_bar[b][slot], 1u);
        while (g_bar[b][slot] < NBLK) { }
        __threadfence();
    }
    __syncthreads();
}

// ---------------------------------------------------------------------------
// MEGA KERNEL: CTAs 0..NSIDE-1 run topk+gather+GEMM1+GEMM2 (spin-barriered
// per batch); CTAs NSIDE.. run the bulk copy. All CTAs co-resident.
// ---------------------------------------------------------------------------
__global__ void __launch_bounds__(512, 2)
mega_kernel(const float4* __restrict__ xv, float4* __restrict__ outv,
            const float* __restrict__ x,
            const float* __restrict__ edge,
            const float* __restrict__ W,
            const float* __restrict__ ga, const float* __restrict__ ba,
            const float* __restrict__ ma, const float* __restrict__ va,
            const float* __restrict__ Wg,
            const float* __restrict__ gw, const float* __restrict__ bw,
            const float* __restrict__ mw, const float* __restrict__ vw) {
    const int blk = blockIdx.x;
    const int t   = threadIdx.x;

    // ======================= COPY ROLE =======================
    if (blk >= NSIDE) {
        const int n4 = Bn * Cn * HWn / 4;
        int i = (blk - NSIDE) * 512 + t;
        const int stride = NCOPY * 512;
        #pragma unroll 4
        for (; i < n4; i += stride) outv[i] = xv[i];
        return;
    }

    // ======================= SIDE ROLE =======================
    const int b   = blk >> 4;     // batch
    const int sub = blk & 15;     // 0..15 within batch
    const int lane = t & 31;
    const int w    = t >> 5;      // 0..15

    __shared__ unsigned int warpsum[16];
    __shared__ unsigned int warpsuf[16];
    __shared__ int sh_cbin;
    __shared__ unsigned int sh_krem;
    __shared__ unsigned int bins[64];
    __shared__ ull skeys[Pn];
    __shared__ __align__(16) float sA[2][32][65];
    __shared__ __align__(16) float sB[2][32][68];

    // ---- load 8 elements/thread; keys live in registers ----
    const int ibase = sub * 4096 + t * 8;
    const float4 e0 = *(const float4*)&edge[(size_t)b * HWn + ibase];
    const float4 e1 = *(const float4*)&edge[(size_t)b * HWn + ibase + 4];
    ull key[8];
    key[0] = make_key(e0.x, ibase + 0); key[1] = make_key(e0.y, ibase + 1);
    key[2] = make_key(e0.z, ibase + 2); key[3] = make_key(e0.w, ibase + 3);
    key[4] = make_key(e1.x, ibase + 4); key[5] = make_key(e1.y, ibase + 5);
    key[6] = make_key(e1.z, ibase + 6); key[7] = make_key(e1.w, ibase + 7);

    int slot = 0;
    #pragma unroll
    for (int pass = 2; pass >= 0; --pass) {
        // ---- histogram (fine + coarse), warp-aggregated atomics ----
        const ull pre = (pass == 2) ? 0ull : *(volatile ull*)&g_prefix[b];
        #pragma unroll
        for (int j = 0; j < 8; ++j) {
            const bool active = (pass == 2) ||
                                ((key[j] >> ((pass + 1) * 16)) == pre);
            const unsigned int bin =
                (unsigned int)((key[j] >> (pass * 16)) & 0xFFFFull);
            const unsigned int amask = __ballot_sync(0xFFFFFFFFu, active);
            if (active) {
                unsigned int peers = __match_any_sync(amask, bin);
                if (lane == __ffs(peers) - 1)
                    atomicAdd(&g_hist[pass][b][bin], (unsigned int)__popc(peers));
                unsigned int peersc = __match_any_sync(amask, bin >> 6);
                if (lane == __ffs(peersc) - 1)
                    atomicAdd(&g_coarse[pass][b][bin >> 6], (unsigned int)__popc(peersc));
            }
        }

        batch_barrier(b, slot++);

        // ---- scan (sub==0): locate digit containing rank K ----
        if (sub == 0) {
            const unsigned int c0 = g_coarse[pass][b][2 * t];
            const unsigned int c1 = g_coarse[pass][b][2 * t + 1];
            const unsigned int mine = c0 + c1;

            unsigned int suf = mine;
            #pragma unroll
            for (int off = 1; off < 32; off <<= 1) {
                const unsigned int v = __shfl_down_sync(0xFFFFFFFFu, suf, off);
                if (lane + off < 32) suf += v;
            }
            if (lane == 0) warpsum[w] = suf;
            __syncthreads();

            if (w == 0) {
                const unsigned int ws = (lane < 16) ? warpsum[lane] : 0u;
                unsigned int wsuf = ws;
                #pragma unroll
                for (int off = 1; off < 32; off <<= 1) {
                    const unsigned int v = __shfl_down_sync(0xFFFFFFFFu, wsuf, off);
                    if (lane + off < 32) wsuf += v;
                }
                if (lane < 16) warpsuf[lane] = wsuf - ws;
            }
            __syncthreads();

            const unsigned int K = (unsigned int)g_K[b];
            const unsigned int suf_t = suf + warpsuf[w];
            const unsigned int above = suf_t - mine;
            if (suf_t >= K && above < K) {
                const unsigned int kp = K - above;
                if (kp <= c1) { sh_cbin = 2 * t + 1; sh_krem = kp; }
                else          { sh_cbin = 2 * t;     sh_krem = kp - c1; }
            }
            __syncthreads();

            const int cbin = sh_cbin;
            if (t < 64) bins[t] = g_hist[pass][b][cbin * 64 + t];
            __syncthreads();

            if (w == 0) {
                const unsigned int krem = sh_krem;
                const unsigned int lo = bins[lane];
                const unsigned int hi = bins[lane + 32];

                unsigned int suf_hi = hi;
                #pragma unroll
                for (int off = 1; off < 32; off <<= 1) {
                    const unsigned int v = __shfl_down_sync(0xFFFFFFFFu, suf_hi, off);
                    if (lane + off < 32) suf_hi += v;
                }
                const unsigned int hi_total = __shfl_sync(0xFFFFFFFFu, suf_hi, 0);

                unsigned int suf_lo = lo;
                #pragma unroll
                for (int off = 1; off < 32; off <<= 1) {
                    const unsigned int v = __shfl_down_sync(0xFFFFFFFFu, suf_lo, off);
                    if (lane + off < 32) suf_lo += v;
                }
                suf_lo += hi_total;

                { const unsigned int st = suf_hi, ab = st - hi;
                  if (st >= krem && ab < krem) {
                      g_prefix[b] = (g_prefix[b] << 16) | (ull)(cbin * 64 + 32 + lane);
                      g_K[b] = (int)(krem - ab);
                  } }
                { const unsigned int st = suf_lo, ab = st - lo;
                  if (st >= krem && ab < krem) {
                      g_prefix[b] = (g_prefix[b] << 16) | (ull)(cbin * 64 + lane);
                      g_K[b] = (int)(krem - ab);
                  } }
            }
            __syncthreads();
        }

        batch_barrier(b, slot++);
    }

    // ---- collect the exact 256 winners ----
    const ull cutoff = *(volatile ull*)&g_prefix[b];
    #pragma unroll
    for (int j = 0; j < 8; ++j) {
        if (key[j] >= cutoff) {
            const int p = atomicAdd(&g_candcnt[b], 1);
            if (p < Pn) g_cand[b][p] = key[j];
        }
    }

    batch_barrier(b, slot++);   // slot 6

    // ---- restore histograms (all 16 CTAs); sub 0 sorts + emits indices ----
    {
        const int base = sub * 512 + t;          // 0..8191
        #pragma unroll
        for (int p = 0; p < 3; ++p) {
            #pragma unroll
            for (int r = 0; r < 8; ++r)
                g_hist[p][b][base + r * 8192] = 0u;
            if (base < 1024) g_coarse[p][b][base] = 0u;
        }
    }
    if (sub == 0) {
        if (t < Pn) skeys[t] = g_cand[b][t];
        __syncthreads();
        for (int kk = 2; kk <= Pn; kk <<= 1) {
            for (int jj = kk >> 1; jj > 0; jj >>= 1) {
                if (t < Pn) {
                    const int ixj = t ^ jj;
                    if (ixj > t) {
                        const ull a = skeys[t];
                        const ull c = skeys[ixj];
                        const bool up = ((t & kk) == 0);
                        if (up ? (a < c) : (a > c)) { skeys[t] = c; skeys[ixj] = a; }
                    }
                }
                __syncthreads();
            }
        }
        if (t < Pn)
            g_idx[b * Pn + t] = (int)(0xFFFFu - (unsigned int)(skeys[t] & 0xFFFFull));
        if (t == 0) {
            g_candcnt[b] = 0;
            g_prefix[b] = 0ull;
            g_K[b] = Pn;
        }
    }

    batch_barrier(b, slot++);   // slot 7: g_idx ready

    // ---- gather: CTA handles n-rows [sub*16, sub*16+16) ----
    {
        float* F = g_feat + b * Pn * Cn;
        const int n  = sub * 16 + (t >> 5);
        const int d0 = lane * 8;
        const int col = g_idx[b * Pn + n];
        const float* xp = x + (size_t)b * Cn * HWn + col;
        float4 v0, v1;
        v0.x = xp[(size_t)(d0 + 0) * HWn];
        v0.y = xp[(size_t)(d0 + 1) * HWn];
        v0.z = xp[(size_t)(d0 + 2) * HWn];
        v0.w = xp[(size_t)(d0 + 3) * HWn];
        v1.x = xp[(size_t)(d0 + 4) * HWn];
        v1.y = xp[(size_t)(d0 + 5) * HWn];
        v1.z = xp[(size_t)(d0 + 6) * HWn];
        v1.w = xp[(size_t)(d0 + 7) * HWn];
        *(float4*)&F[n * Cn + d0]     = v0;
        *(float4*)&F[n * Cn + d0 + 4] = v1;
    }

    batch_barrier(b, slot++);   // slot 8: F ready

    // ---- GEMM1 tile (64x64, KB=32, double-buffered) ----
    const int ti = (sub >> 2) * 64;
    const int td = (sub & 3) * 64;
    const int tx = t & 15;
    const int ty = t >> 4;      // 0..31

    {
        const float* F = g_feat + b * Pn * Cn;
        float* Z       = g_z    + b * Pn * Cn;
        const int ai = t >> 3, ak = (t & 7) * 4;      // A: 64x32, 1 f4/thread
        const int bk = t >> 4, bd = (t & 15) * 4;     // B: 32x64, 1 f4/thread

        float4 na, nb;
        float acc[2][4] = {};

        na = *(const float4*)&W[(ti + ai) * Pn + ak];
        nb = *(const float4*)&F[bk * Cn + td + bd];
        sA[0][ak + 0][ai] = na.x; sA[0][ak + 1][ai] = na.y;
        sA[0][ak + 2][ai] = na.z; sA[0][ak + 3][ai] = na.w;
        *(float4*)&sB[0][bk][bd] = nb;
        __syncthreads();

        #pragma unroll
        for (int kt = 0; kt < 8; ++kt) {
            const int st = kt & 1;
            if (kt < 7) {
                const int k0 = (kt + 1) * 32;
                na = *(const float4*)&W[(ti + ai) * Pn + k0 + ak];
                nb = *(const float4*)&F[(k0 + bk) * Cn + td + bd];
            }
            #pragma unroll
            for (int k = 0; k < 32; ++k) {
                const float a0 = sA[st][k][ty * 2 + 0];
                const float a1 = sA[st][k][ty * 2 + 1];
                const float4 b4 = *(const float4*)&sB[st][k][tx * 4];
                acc[0][0] += a0 * b4.x; acc[0][1] += a0 * b4.y;
                acc[0][2] += a0 * b4.z; acc[0][3] += a0 * b4.w;
                acc[1][0] += a1 * b4.x; acc[1][1] += a1 * b4.y;
                acc[1][2] += a1 * b4.z; acc[1][3] += a1 * b4.w;
            }
            if (kt < 7) {
                const int sn = st ^ 1;
                sA[sn][ak + 0][ai] = na.x; sA[sn][ak + 1][ai] = na.y;
                sA[sn][ak + 2][ai] = na.z; sA[sn][ak + 3][ai] = na.w;
                *(float4*)&sB[sn][bk][bd] = nb;
            }
            __syncthreads();
        }

        const int d = td + tx * 4;
        #pragma unroll
        for (int ui = 0; ui < 2; ++ui) {
            const int i = ti + ty * 2 + ui;
            const float inv = ga[i] * rsqrtf(va[i] + EPSn);
            const float add = ba[i] - ma[i] * inv;
            const float4 f4 = *(const float4*)&F[i * Cn + d];
            float4 o;
            o.x = fmaxf(acc[ui][0] * inv + add, 0.0f) + f4.x;
            o.y = fmaxf(acc[ui][1] * inv + add, 0.0f) + f4.y;
            o.z = fmaxf(acc[ui][2] * inv + add, 0.0f) + f4.z;
            o.w = fmaxf(acc[ui][3] * inv + add, 0.0f) + f4.w;
            *(float4*)&Z[i * Cn + d] = o;
        }
    }

    batch_barrier(b, slot++);   // slot 9: Z ready

    // ---- GEMM2 tile (NT, 64x64, KB=32, double-buffered) ----
    {
        const float* Z = g_z  + b * Pn * Cn;
        float* Z2      = g_z2 + b * Pn * Cn;
        const int tp = ti;      // reuse row group
        const int tc = td;      // reuse col group
        const int ar = t >> 3, ak = (t & 7) * 4;

        float4 na, nb;
        float acc[2][4] = {};

        na = *(const float4*)&Z[(tp + ar) * Cn + ak];
        nb = *(const float4*)&Wg[(tc + ar) * Cn + ak];
        sA[0][ak + 0][ar] = na.x; sA[0][ak + 1][ar] = na.y;
        sA[0][ak + 2][ar] = na.z; sA[0][ak + 3][ar] = na.w;
        sB[0][ak + 0][ar] = nb.x; sB[0][ak + 1][ar] = nb.y;
        sB[0][ak + 2][ar] = nb.z; sB[0][ak + 3][ar] = nb.w;
        __syncthreads();

        #pragma unroll
        for (int kt = 0; kt < 8; ++kt) {
            const int st = kt & 1;
            if (kt < 7) {
                const int k0 = (kt + 1) * 32;
                na = *(const float4*)&Z[(tp + ar) * Cn + k0 + ak];
                nb = *(const float4*)&Wg[(tc + ar) * Cn + k0 + ak];
            }
            #pragma unroll
            for (int k = 0; k < 32; ++k) {
                const float a0 = sA[st][k][ty * 2 + 0];
                const float a1 = sA[st][k][ty * 2 + 1];
                const float4 b4 = *(const float4*)&sB[st][k][tx * 4];
                acc[0][0] += a0 * b4.x; acc[0][1] += a0 * b4.y;
                acc[0][2] += a0 * b4.z; acc[0][3] += a0 * b4.w;
                acc[1][0] += a1 * b4.x; acc[1][1] += a1 * b4.y;
                acc[1][2] += a1 * b4.z; acc[1][3] += a1 * b4.w;
            }
            if (kt < 7) {
                const int sn = st ^ 1;
                sA[sn][ak + 0][ar] = na.x; sA[sn][ak + 1][ar] = na.y;
                sA[sn][ak + 2][ar] = na.z; sA[sn][ak + 3][ar] = na.w;
                sB[sn][ak + 0][ar] = nb.x; sB[sn][ak + 1][ar] = nb.y;
                sB[sn][ak + 2][ar] = nb.z; sB[sn][ak + 3][ar] = nb.w;
            }
            __syncthreads();
        }

        #pragma unroll
        for (int uc = 0; uc < 4; ++uc) {
            const int c = tc + tx * 4 + uc;
            const float inv = gw[c] * rsqrtf(vw[c] + EPSn);
            const float add = bw[c] - mw[c] * inv;
            #pragma unroll
            for (int ui = 0; ui < 2; ++ui) {
                const int p = tp + ty * 2 + ui;
                Z2[p * Cn + c] = fmaxf(acc[ui][uc] * inv + add, 0.0f);
            }
        }
    }
    // g_bar reset happens in scatter_kernel (strictly after this kernel).
}

// ---------------------------------------------------------------------------
// Scatter: out[b, c, idx[b,p]] = z2[b,p,c].  grid (Pn, Bn), 256 threads (c).
// Also resets all spin-barrier counters for the next graph replay.
// ---------------------------------------------------------------------------
__global__ void __launch_bounds__(256)
scatter_kernel(float* __restrict__ out) {
    const int b = blockIdx.y;
    const int p = blockIdx.x;
    const int c = threadIdx.x;
    if (p == 0 && c < 12) g_bar[b][c] = 0u;
    const int col = g_idx[b * Pn + p];
    out[(size_t)b * Cn * HWn + (size_t)c * HWn + (size_t)col] =
        g_z2[((b * Pn + p) << 8) + c];
}

// ---------------------------------------------------------------------------
extern "C" void kernel_launch(void* const* d_in, const int* in_sizes, int n_in,
                              void* d_out, int out_size) {
    const float* x     = (const float*)d_in[0];
    const float* edge  = (const float*)d_in[1];
    const float* w_adj = (const float*)d_in[2];
    const float* g_adj = (const float*)d_in[3];
    const float* b_adj = (const float*)d_in[4];
    const float* m_adj = (const float*)d_in[5];
    const float* v_adj = (const float*)d_in[6];
    const float* w_wg  = (const float*)d_in[7];
    const float* g_wg  = (const float*)d_in[8];
    const float* b_wg  = (const float*)d_in[9];
    const float* m_wg  = (const float*)d_in[10];
    const float* v_wg  = (const float*)d_in[11];
    float* out = (float*)d_out;

    // One launch does copy + topk + gather + both GEMMs (role-split CTAs,
    // all co-resident), then scatter joins the results into out.
    mega_kernel<<<NTOT, 512>>>((const float4*)x, (float4*)out,
                               x, edge,
                               w_adj, g_adj, b_adj, m_adj, v_adj,
                               w_wg, g_wg, b_wg, m_wg, v_wg);
    scatter_kernel<<<dim3(Pn, Bn), 256>>>(out);
}

// round 14
// speedup vs baseline: 1.2887x; 1.0031x over previous
#include <cuda_runtime.h>
#include <math.h>

// Problem dims (fixed by the dataset)
#define Bn   4
#define Cn   256
#define HWn  65536
#define Pn   256
#define THRESH_F 0.8f
#define EPSn 1e-5f

typedef unsigned long long ull;

// ---------------------------------------------------------------------------
// Scratch (no cudaMalloc). All state reset in-kernel for graph replay.
// ---------------------------------------------------------------------------
__device__ __align__(16) int   g_idx[Bn * Pn];
__device__ __align__(16) float g_feat[Bn * Pn * Cn];   // (B, P, C)
__device__ __align__(16) float g_z[Bn * Pn * Cn];      // (B, P, C)
__device__ __align__(16) float g_z2[Bn * Pn * Cn];     // (B, P, C)

__device__ unsigned int g_hist[3][Bn][65536];    // zero at rest
__device__ unsigned int g_coarse[3][Bn][1024];   // zero at rest
__device__ ull g_prefix[Bn];                     // zero at rest
__device__ int g_K[Bn] = {Pn, Pn, Pn, Pn};       // Pn at rest
__device__ int g_candcnt[Bn];                    // zero at rest
__device__ ull g_cand[Bn][Pn];
__device__ volatile unsigned int g_bar[Bn][12];  // zero at rest
__device__ unsigned int g_chunk;                 // zero at rest
__device__ volatile unsigned int g_copydone;     // zero at rest
__device__ unsigned int g_scatdone;              // zero at rest

#define NSIDE 64                 // 16 side CTAs per batch
#define NCOPY 224
#define NTOT  (NSIDE + NCOPY)    // 288 <= 296 co-resident
#define NBLK  16
#define CHUNK_F4 4096            // 64 KB chunks
#define NCHUNKS (Bn * Cn * HWn / 4 / CHUNK_F4)   // 4096

// ---------------------------------------------------------------------------
// 48-bit composite key: (monotone_float32 << 16) | (0xFFFF - idx)
// ---------------------------------------------------------------------------
__device__ __forceinline__ ull make_key(float e, int i) {
    float v = (e < THRESH_F) ? 0.0f : e;
    unsigned int ub = __float_as_uint(v);
    ub = (ub & 0x80000000u) ? ~ub : (ub | 0x80000000u);
    return ((ull)ub << 16) | (ull)(0xFFFFu - (unsigned int)i);
}

// Per-batch spin barrier over the NBLK side CTAs of batch b.
__device__ __forceinline__ void batch_barrier(int b, int slot) {
    __threadfence();
    __syncthreads();
    if (threadIdx.x == 0) {
        atomicAdd((unsigned int*)&g_bar[b][slot], 1u);
        while (g_bar[b][slot] < NBLK) { }
        __threadfence();
    }
    __syncthreads();
}

// Work-stealing copy: grab 64 KB chunks until exhausted. CTA-wide.
__device__ __forceinline__ void copy_worker(const float4* __restrict__ src,
                                            float4* __restrict__ dst) {
    __shared__ unsigned int sh_c;
    for (;;) {
        __syncthreads();
        if (threadIdx.x == 0) sh_c = atomicAdd(&g_chunk, 1u);
        __syncthreads();
        const unsigned int c = sh_c;
        if (c >= NCHUNKS) break;
        const int base = c * CHUNK_F4 + threadIdx.x;
        #pragma unroll
        for (int j = 0; j < 8; ++j)
            dst[base + j * 512] = src[base + j * 512];
    }
}

// ---------------------------------------------------------------------------
// MEGA KERNEL: CTAs 0..NSIDE-1: topk+gather+GEMM1+GEMM2, then join copy,
// wait for copy completion, scatter. CTAs NSIDE..: work-steal copy.
// ---------------------------------------------------------------------------
__global__ void __launch_bounds__(512, 2)
mega_kernel(const float4* __restrict__ xv, float4* __restrict__ outv,
            const float* __restrict__ x,
            const float* __restrict__ edge,
            const float* __restrict__ W,
            const float* __restrict__ ga, const float* __restrict__ ba,
            const float* __restrict__ ma, const float* __restrict__ va,
            const float* __restrict__ Wg,
            const float* __restrict__ gw, const float* __restrict__ bw,
            const float* __restrict__ mw, const float* __restrict__ vw,
            float* __restrict__ out) {
    const int blk = blockIdx.x;
    const int t   = threadIdx.x;

    // ======================= COPY ROLE =======================
    if (blk >= NSIDE) {
        copy_worker(xv, outv);
        __threadfence();
        __syncthreads();
        if (t == 0) atomicAdd((unsigned int*)&g_copydone, 1u);
        return;
    }

    // ======================= SIDE ROLE =======================
    const int b   = blk >> 4;
    const int sub = blk & 15;
    const int lane = t & 31;
    const int w    = t >> 5;

    __shared__ unsigned int warpsum[16];
    __shared__ unsigned int warpsuf[16];
    __shared__ int sh_cbin;
    __shared__ unsigned int sh_krem;
    __shared__ unsigned int bins[64];
    __shared__ ull skeys[Pn];
    __shared__ __align__(16) float sA[2][32][65];
    __shared__ __align__(16) float sB[2][32][68];

    // ---- keys in registers (8/thread) ----
    const int ibase = sub * 4096 + t * 8;
    const float4 e0 = *(const float4*)&edge[(size_t)b * HWn + ibase];
    const float4 e1 = *(const float4*)&edge[(size_t)b * HWn + ibase + 4];
    ull key[8];
    key[0] = make_key(e0.x, ibase + 0); key[1] = make_key(e0.y, ibase + 1);
    key[2] = make_key(e0.z, ibase + 2); key[3] = make_key(e0.w, ibase + 3);
    key[4] = make_key(e1.x, ibase + 4); key[5] = make_key(e1.y, ibase + 5);
    key[6] = make_key(e1.z, ibase + 6); key[7] = make_key(e1.w, ibase + 7);

    int slot = 0;
    #pragma unroll
    for (int pass = 2; pass >= 0; --pass) {
        const ull pre = (pass == 2) ? 0ull : *(volatile ull*)&g_prefix[b];
        #pragma unroll
        for (int j = 0; j < 8; ++j) {
            const bool active = (pass == 2) ||
                                ((key[j] >> ((pass + 1) * 16)) == pre);
            const unsigned int bin =
                (unsigned int)((key[j] >> (pass * 16)) & 0xFFFFull);
            const unsigned int amask = __ballot_sync(0xFFFFFFFFu, active);
            if (active) {
                unsigned int peers = __match_any_sync(amask, bin);
                if (lane == __ffs(peers) - 1)
                    atomicAdd(&g_hist[pass][b][bin], (unsigned int)__popc(peers));
                unsigned int peersc = __match_any_sync(amask, bin >> 6);
                if (lane == __ffs(peersc) - 1)
                    atomicAdd(&g_coarse[pass][b][bin >> 6], (unsigned int)__popc(peersc));
            }
        }

        batch_barrier(b, slot++);

        if (sub == 0) {
            const unsigned int c0 = g_coarse[pass][b][2 * t];
            const unsigned int c1 = g_coarse[pass][b][2 * t + 1];
            const unsigned int mine = c0 + c1;

            unsigned int suf = mine;
            #pragma unroll
            for (int off = 1; off < 32; off <<= 1) {
                const unsigned int v = __shfl_down_sync(0xFFFFFFFFu, suf, off);
                if (lane + off < 32) suf += v;
            }
            if (lane == 0) warpsum[w] = suf;
            __syncthreads();

            if (w == 0) {
                const unsigned int ws = (lane < 16) ? warpsum[lane] : 0u;
                unsigned int wsuf = ws;
                #pragma unroll
                for (int off = 1; off < 32; off <<= 1) {
                    const unsigned int v = __shfl_down_sync(0xFFFFFFFFu, wsuf, off);
                    if (lane + off < 32) wsuf += v;
                }
                if (lane < 16) warpsuf[lane] = wsuf - ws;
            }
            __syncthreads();

            const unsigned int K = (unsigned int)g_K[b];
            const unsigned int suf_t = suf + warpsuf[w];
            const unsigned int above = suf_t - mine;
            if (suf_t >= K && above < K) {
                const unsigned int kp = K - above;
                if (kp <= c1) { sh_cbin = 2 * t + 1; sh_krem = kp; }
                else          { sh_cbin = 2 * t;     sh_krem = kp - c1; }
            }
            __syncthreads();

            const int cbin = sh_cbin;
            if (t < 64) bins[t] = g_hist[pass][b][cbin * 64 + t];
            __syncthreads();

            if (w == 0) {
                const unsigned int krem = sh_krem;
                const unsigned int lo = bins[lane];
                const unsigned int hi = bins[lane + 32];

                unsigned int suf_hi = hi;
                #pragma unroll
                for (int off = 1; off < 32; off <<= 1) {
                    const unsigned int v = __shfl_down_sync(0xFFFFFFFFu, suf_hi, off);
                    if (lane + off < 32) suf_hi += v;
                }
                const unsigned int hi_total = __shfl_sync(0xFFFFFFFFu, suf_hi, 0);

                unsigned int suf_lo = lo;
                #pragma unroll
                for (int off = 1; off < 32; off <<= 1) {
                    const unsigned int v = __shfl_down_sync(0xFFFFFFFFu, suf_lo, off);
                    if (lane + off < 32) suf_lo += v;
                }
                suf_lo += hi_total;

                { const unsigned int st = suf_hi, ab = st - hi;
                  if (st >= krem && ab < krem) {
                      g_prefix[b] = (g_prefix[b] << 16) | (ull)(cbin * 64 + 32 + lane);
                      g_K[b] = (int)(krem - ab);
                  } }
                { const unsigned int st = suf_lo, ab = st - lo;
                  if (st >= krem && ab < krem) {
                      g_prefix[b] = (g_prefix[b] << 16) | (ull)(cbin * 64 + lane);
                      g_K[b] = (int)(krem - ab);
                  } }
            }
            __syncthreads();
        }

        batch_barrier(b, slot++);
    }

    // ---- collect ----
    const ull cutoff = *(volatile ull*)&g_prefix[b];
    #pragma unroll
    for (int j = 0; j < 8; ++j) {
        if (key[j] >= cutoff) {
            const int p = atomicAdd(&g_candcnt[b], 1);
            if (p < Pn) g_cand[b][p] = key[j];
        }
    }

    batch_barrier(b, slot++);   // slot 6

    // ---- restore histograms; sub 0 sorts + emits indices ----
    {
        const int base = sub * 512 + t;
        #pragma unroll
        for (int p = 0; p < 3; ++p) {
            #pragma unroll
            for (int r = 0; r < 8; ++r)
                g_hist[p][b][base + r * 8192] = 0u;
            if (base < 1024) g_coarse[p][b][base] = 0u;
        }
    }
    if (sub == 0) {
        if (t < Pn) skeys[t] = g_cand[b][t];
        __syncthreads();
        for (int kk = 2; kk <= Pn; kk <<= 1) {
            for (int jj = kk >> 1; jj > 0; jj >>= 1) {
                if (t < Pn) {
                    const int ixj = t ^ jj;
                    if (ixj > t) {
                        const ull a = skeys[t];
                        const ull c = skeys[ixj];
                        const bool up = ((t & kk) == 0);
                        if (up ? (a < c) : (a > c)) { skeys[t] = c; skeys[ixj] = a; }
                    }
                }
                __syncthreads();
            }
        }
        if (t < Pn)
            g_idx[b * Pn + t] = (int)(0xFFFFu - (unsigned int)(skeys[t] & 0xFFFFull));
        if (t == 0) {
            g_candcnt[b] = 0;
            g_prefix[b] = 0ull;
            g_K[b] = Pn;
        }
    }

    batch_barrier(b, slot++);   // slot 7: g_idx ready

    // ---- gather: n-rows [sub*16, sub*16+16) ----
    {
        float* F = g_feat + b * Pn * Cn;
        const int n  = sub * 16 + (t >> 5);
        const int d0 = lane * 8;
        const int col = g_idx[b * Pn + n];
        const float* xp = x + (size_t)b * Cn * HWn + col;
        float4 v0, v1;
        v0.x = xp[(size_t)(d0 + 0) * HWn];
        v0.y = xp[(size_t)(d0 + 1) * HWn];
        v0.z = xp[(size_t)(d0 + 2) * HWn];
        v0.w = xp[(size_t)(d0 + 3) * HWn];
        v1.x = xp[(size_t)(d0 + 4) * HWn];
        v1.y = xp[(size_t)(d0 + 5) * HWn];
        v1.z = xp[(size_t)(d0 + 6) * HWn];
        v1.w = xp[(size_t)(d0 + 7) * HWn];
        *(float4*)&F[n * Cn + d0]     = v0;
        *(float4*)&F[n * Cn + d0 + 4] = v1;
    }

    batch_barrier(b, slot++);   // slot 8: F ready

    const int ti = (sub >> 2) * 64;
    const int td = (sub & 3) * 64;
    const int tx = t & 15;
    const int ty = t >> 4;

    // ---- GEMM1 (64x64, KB=32, double-buffered) ----
    {
        const float* F = g_feat + b * Pn * Cn;
        float* Z       = g_z    + b * Pn * Cn;
        const int ai = t >> 3, ak = (t & 7) * 4;
        const int bk = t >> 4, bd = (t & 15) * 4;

        float4 na, nb;
        float acc[2][4] = {};

        na = *(const float4*)&W[(ti + ai) * Pn + ak];
        nb = *(const float4*)&F[bk * Cn + td + bd];
        sA[0][ak + 0][ai] = na.x; sA[0][ak + 1][ai] = na.y;
        sA[0][ak + 2][ai] = na.z; sA[0][ak + 3][ai] = na.w;
        *(float4*)&sB[0][bk][bd] = nb;
        __syncthreads();

        #pragma unroll
        for (int kt = 0; kt < 8; ++kt) {
            const int st = kt & 1;
            if (kt < 7) {
                const int k0 = (kt + 1) * 32;
                na = *(const float4*)&W[(ti + ai) * Pn + k0 + ak];
                nb = *(const float4*)&F[(k0 + bk) * Cn + td + bd];
            }
            #pragma unroll
            for (int k = 0; k < 32; ++k) {
                const float a0 = sA[st][k][ty * 2 + 0];
                const float a1 = sA[st][k][ty * 2 + 1];
                const float4 b4 = *(const float4*)&sB[st][k][tx * 4];
                acc[0][0] += a0 * b4.x; acc[0][1] += a0 * b4.y;
                acc[0][2] += a0 * b4.z; acc[0][3] += a0 * b4.w;
                acc[1][0] += a1 * b4.x; acc[1][1] += a1 * b4.y;
                acc[1][2] += a1 * b4.z; acc[1][3] += a1 * b4.w;
            }
            if (kt < 7) {
                const int sn = st ^ 1;
                sA[sn][ak + 0][ai] = na.x; sA[sn][ak + 1][ai] = na.y;
                sA[sn][ak + 2][ai] = na.z; sA[sn][ak + 3][ai] = na.w;
                *(float4*)&sB[sn][bk][bd] = nb;
            }
            __syncthreads();
        }

        const int d = td + tx * 4;
        #pragma unroll
        for (int ui = 0; ui < 2; ++ui) {
            const int i = ti + ty * 2 + ui;
            const float inv = ga[i] * rsqrtf(va[i] + EPSn);
            const float add = ba[i] - ma[i] * inv;
            const float4 f4 = *(const float4*)&F[i * Cn + d];
            float4 o;
            o.x = fmaxf(acc[ui][0] * inv + add, 0.0f) + f4.x;
            o.y = fmaxf(acc[ui][1] * inv + add, 0.0f) + f4.y;
            o.z = fmaxf(acc[ui][2] * inv + add, 0.0f) + f4.z;
            o.w = fmaxf(acc[ui][3] * inv + add, 0.0f) + f4.w;
            *(float4*)&Z[i * Cn + d] = o;
        }
    }

    batch_barrier(b, slot++);   // slot 9: Z ready

    // ---- GEMM2 (NT, 64x64, KB=32, double-buffered) ----
    {
        const float* Z = g_z  + b * Pn * Cn;
        float* Z2      = g_z2 + b * Pn * Cn;
        const int ar = t >> 3, ak = (t & 7) * 4;

        float4 na, nb;
        float acc[2][4] = {};

        na = *(const float4*)&Z[(ti + ar) * Cn + ak];
        nb = *(const float4*)&Wg[(td + ar) * Cn + ak];
        sA[0][ak + 0][ar] = na.x; sA[0][ak + 1][ar] = na.y;
        sA[0][ak + 2][ar] = na.z; sA[0][ak + 3][ar] = na.w;
        sB[0][ak + 0][ar] = nb.x; sB[0][ak + 1][ar] = nb.y;
        sB[0][ak + 2][ar] = nb.z; sB[0][ak + 3][ar] = nb.w;
        __syncthreads();

        #pragma unroll
        for (int kt = 0; kt < 8; ++kt) {
            const int st = kt & 1;
            if (kt < 7) {
                const int k0 = (kt + 1) * 32;
                na = *(const float4*)&Z[(ti + ar) * Cn + k0 + ak];
                nb = *(const float4*)&Wg[(td + ar) * Cn + k0 + ak];
            }
            #pragma unroll
            for (int k = 0; k < 32; ++k) {
                const float a0 = sA[st][k][ty * 2 + 0];
                const float a1 = sA[st][k][ty * 2 + 1];
                const float4 b4 = *(const float4*)&sB[st][k][tx * 4];
                acc[0][0] += a0 * b4.x; acc[0][1] += a0 * b4.y;
                acc[0][2] += a0 * b4.z; acc[0][3] += a0 * b4.w;
                acc[1][0] += a1 * b4.x; acc[1][1] += a1 * b4.y;
                acc[1][2] += a1 * b4.z; acc[1][3] += a1 * b4.w;
            }
            if (kt < 7) {
                const int sn = st ^ 1;
                sA[sn][ak + 0][ar] = na.x; sA[sn][ak + 1][ar] = na.y;
                sA[sn][ak + 2][ar] = na.z; sA[sn][ak + 3][ar] = na.w;
                sB[sn][ak + 0][ar] = nb.x; sB[sn][ak + 1][ar] = nb.y;
                sB[sn][ak + 2][ar] = nb.z; sB[sn][ak + 3][ar] = nb.w;
            }
            __syncthreads();
        }

        #pragma unroll
        for (int uc = 0; uc < 4; ++uc) {
            const int c = td + tx * 4 + uc;
            const float inv = gw[c] * rsqrtf(vw[c] + EPSn);
            const float add = bw[c] - mw[c] * inv;
            #pragma unroll
            for (int ui = 0; ui < 2; ++ui) {
                const int p = ti + ty * 2 + ui;
                Z2[p * Cn + c] = fmaxf(acc[ui][uc] * inv + add, 0.0f);
            }
        }
    }

    batch_barrier(b, slot++);   // slot 10: z2 fully written (this batch)

    // ---- join the copy, then signal done ----
    copy_worker(xv, outv);
    __threadfence();
    __syncthreads();
    if (t == 0) atomicAdd((unsigned int*)&g_copydone, 1u);

    // ---- wait until the whole copy is complete (all 288 CTAs) ----
    if (t == 0) {
        while (g_copydone < NTOT) { }
        __threadfence();
    }
    __syncthreads();

    // ---- scatter: out[b, c, idx[b,p]] = z2[b,p,c] for p in [sub*16, +16) ----
    {
        const float* Z2 = g_z2 + b * Pn * Cn;
        const int p   = sub * 16 + (t >> 5);
        const int col = g_idx[b * Pn + p];
        float* op = out + (size_t)b * Cn * HWn + col;
        #pragma unroll
        for (int k = 0; k < 8; ++k) {
            const int c = lane + k * 32;
            op[(size_t)c * HWn] = Z2[p * Cn + c];
        }
    }

    // ---- last scatterer resets all replay state ----
    __threadfence();
    __syncthreads();
    if (t == 0) {
        const unsigned int r = atomicAdd(&g_scatdone, 1u);
        if (r == NSIDE - 1) {
            g_chunk = 0;
            *(unsigned int*)&g_copydone = 0u;
            g_scatdone = 0u;
            for (int bb = 0; bb < Bn; ++bb)
                for (int s = 0; s < 12; ++s) g_bar[bb][s] = 0u;
        }
    }
}

// ---------------------------------------------------------------------------
extern "C" void kernel_launch(void* const* d_in, const int* in_sizes, int n_in,
                              void* d_out, int out_size) {
    const float* x     = (const float*)d_in[0];
    const float* edge  = (const float*)d_in[1];
    const float* w_adj = (const float*)d_in[2];
    const float* g_adj = (const float*)d_in[3];
    const float* b_adj = (const float*)d_in[4];
    const float* m_adj = (const float*)d_in[5];
    const float* v_adj = (const float*)d_in[6];
    const float* w_wg  = (const float*)d_in[7];
    const float* g_wg  = (const float*)d_in[8];
    const float* b_wg  = (const float*)d_in[9];
    const float* m_wg  = (const float*)d_in[10];
    const float* v_wg  = (const float*)d_in[11];
    float* out = (float*)d_out;

    // Single launch: role-split CTAs do copy + topk + gather + GEMMs + scatter.
    mega_kernel<<<NTOT, 512>>>((const float4*)x, (float4*)out,
                               x, edge,
                               w_adj, g_adj, b_adj, m_adj, v_adj,
                               w_wg, g_wg, b_wg, m_wg, v_wg,
                               out);
}

// round 15
// speedup vs baseline: 1.2902x; 1.0012x over previous
#include <cuda_runtime.h>
#include <math.h>

// Problem dims (fixed by the dataset)
#define Bn   4
#define Cn   256
#define HWn  65536
#define Pn   256
#define THRESH_F 0.8f
#define EPSn 1e-5f

typedef unsigned long long ull;

// ---------------------------------------------------------------------------
// Scratch (no cudaMalloc). All state reset in-kernel for graph replay.
// ---------------------------------------------------------------------------
__device__ __align__(16) int   g_idx[Bn * Pn];
__device__ __align__(16) float g_feat[Bn * Pn * Cn];   // (B, P, C)
__device__ __align__(16) float g_z[Bn * Pn * Cn];      // (B, P, C)
__device__ __align__(16) float g_z2[Bn * Pn * Cn];     // (B, P, C)

__device__ unsigned int g_hist[3][Bn][65536];    // zero at rest
__device__ unsigned int g_coarse[3][Bn][1024];   // zero at rest
__device__ ull g_prefix[Bn];                     // zero at rest
__device__ int g_K[Bn] = {Pn, Pn, Pn, Pn};       // Pn at rest
__device__ int g_candcnt[Bn];                    // zero at rest
__device__ ull g_cand[Bn][Pn];
__device__ volatile unsigned int g_bar[Bn][12];  // zero at rest
__device__ volatile unsigned int g_copydone;     // zero at rest
__device__ unsigned int g_scatdone;              // zero at rest

#define NSIDE 64                 // 16 side CTAs per batch
#define NCOPY 232
#define NTOT  (NSIDE + NCOPY)    // 296 = 2 CTAs/SM x 148 -> all co-resident
#define NBLK  16

// ---------------------------------------------------------------------------
// 48-bit composite key: (monotone_float32 << 16) | (0xFFFF - idx)
// ---------------------------------------------------------------------------
__device__ __forceinline__ ull make_key(float e, int i) {
    float v = (e < THRESH_F) ? 0.0f : e;
    unsigned int ub = __float_as_uint(v);
    ub = (ub & 0x80000000u) ? ~ub : (ub | 0x80000000u);
    return ((ull)ub << 16) | (ull)(0xFFFFu - (unsigned int)i);
}

// Per-batch spin barrier over the NBLK side CTAs of batch b.
__device__ __forceinline__ void batch_barrier(int b, int slot) {
    __threadfence();
    __syncthreads();
    if (threadIdx.x == 0) {
        atomicAdd((unsigned int*)&g_bar[b][slot], 1u);
        while (g_bar[b][slot] < NBLK) { }
        __threadfence();
    }
    __syncthreads();
}

// ---------------------------------------------------------------------------
// MEGA KERNEL: CTAs 0..NSIDE-1: topk+gather+GEMM1+GEMM2, wait for copy,
// scatter. CTAs NSIDE..: barrier-free grid-stride copy (deep MLP).
// ---------------------------------------------------------------------------
__global__ void __launch_bounds__(512, 2)
mega_kernel(const float4* __restrict__ xv, float4* __restrict__ outv,
            const float* __restrict__ x,
            const float* __restrict__ edge,
            const float* __restrict__ W,
            const float* __restrict__ ga, const float* __restrict__ ba,
            const float* __restrict__ ma, const float* __restrict__ va,
            const float* __restrict__ Wg,
            const float* __restrict__ gw, const float* __restrict__ bw,
            const float* __restrict__ mw, const float* __restrict__ vw,
            float* __restrict__ out) {
    const int blk = blockIdx.x;
    const int t   = threadIdx.x;

    // ======================= COPY ROLE =======================
    if (blk >= NSIDE) {
        const int n4 = Bn * Cn * HWn / 4;     // 16,777,216 float4
        int i = (blk - NSIDE) * 512 + t;
        const int stride = NCOPY * 512;       // 118,784
        #pragma unroll 4
        for (; i < n4; i += stride) outv[i] = xv[i];
        __threadfence();
        __syncthreads();
        if (t == 0) atomicAdd((unsigned int*)&g_copydone, 1u);
        return;
    }

    // ======================= SIDE ROLE =======================
    const int b   = blk >> 4;
    const int sub = blk & 15;
    const int lane = t & 31;
    const int w    = t >> 5;

    __shared__ unsigned int warpsum[16];
    __shared__ unsigned int warpsuf[16];
    __shared__ int sh_cbin;
    __shared__ unsigned int sh_krem;
    __shared__ unsigned int bins[64];
    __shared__ ull skeys[Pn];
    __shared__ __align__(16) float sA[2][32][65];
    __shared__ __align__(16) float sB[2][32][68];

    // ---- keys in registers (8/thread) ----
    const int ibase = sub * 4096 + t * 8;
    const float4 e0 = *(const float4*)&edge[(size_t)b * HWn + ibase];
    const float4 e1 = *(const float4*)&edge[(size_t)b * HWn + ibase + 4];
    ull key[8];
    key[0] = make_key(e0.x, ibase + 0); key[1] = make_key(e0.y, ibase + 1);
    key[2] = make_key(e0.z, ibase + 2); key[3] = make_key(e0.w, ibase + 3);
    key[4] = make_key(e1.x, ibase + 4); key[5] = make_key(e1.y, ibase + 5);
    key[6] = make_key(e1.z, ibase + 6); key[7] = make_key(e1.w, ibase + 7);

    int slot = 0;
    #pragma unroll
    for (int pass = 2; pass >= 0; --pass) {
        const ull pre = (pass == 2) ? 0ull : *(volatile ull*)&g_prefix[b];
        #pragma unroll
        for (int j = 0; j < 8; ++j) {
            const bool active = (pass == 2) ||
                                ((key[j] >> ((pass + 1) * 16)) == pre);
            const unsigned int bin =
                (unsigned int)((key[j] >> (pass * 16)) & 0xFFFFull);
            const unsigned int amask = __ballot_sync(0xFFFFFFFFu, active);
            if (active) {
                unsigned int peers = __match_any_sync(amask, bin);
                if (lane == __ffs(peers) - 1)
                    atomicAdd(&g_hist[pass][b][bin], (unsigned int)__popc(peers));
                unsigned int peersc = __match_any_sync(amask, bin >> 6);
                if (lane == __ffs(peersc) - 1)
                    atomicAdd(&g_coarse[pass][b][bin >> 6], (unsigned int)__popc(peersc));
            }
        }

        batch_barrier(b, slot++);

        if (sub == 0) {
            const unsigned int c0 = g_coarse[pass][b][2 * t];
            const unsigned int c1 = g_coarse[pass][b][2 * t + 1];
            const unsigned int mine = c0 + c1;

            unsigned int suf = mine;
            #pragma unroll
            for (int off = 1; off < 32; off <<= 1) {
                const unsigned int v = __shfl_down_sync(0xFFFFFFFFu, suf, off);
                if (lane + off < 32) suf += v;
            }
            if (lane == 0) warpsum[w] = suf;
            __syncthreads();

            if (w == 0) {
                const unsigned int ws = (lane < 16) ? warpsum[lane] : 0u;
                unsigned int wsuf = ws;
                #pragma unroll
                for (int off = 1; off < 32; off <<= 1) {
                    const unsigned int v = __shfl_down_sync(0xFFFFFFFFu, wsuf, off);
                    if (lane + off < 32) wsuf += v;
                }
                if (lane < 16) warpsuf[lane] = wsuf - ws;
            }
            __syncthreads();

            const unsigned int K = (unsigned int)g_K[b];
            const unsigned int suf_t = suf + warpsuf[w];
            const unsigned int above = suf_t - mine;
            if (suf_t >= K && above < K) {
                const unsigned int kp = K - above;
                if (kp <= c1) { sh_cbin = 2 * t + 1; sh_krem = kp; }
                else          { sh_cbin = 2 * t;     sh_krem = kp - c1; }
            }
            __syncthreads();

            const int cbin = sh_cbin;
            if (t < 64) bins[t] = g_hist[pass][b][cbin * 64 + t];
            __syncthreads();

            if (w == 0) {
                const unsigned int krem = sh_krem;
                const unsigned int lo = bins[lane];
                const unsigned int hi = bins[lane + 32];

                unsigned int suf_hi = hi;
                #pragma unroll
                for (int off = 1; off < 32; off <<= 1) {
                    const unsigned int v = __shfl_down_sync(0xFFFFFFFFu, suf_hi, off);
                    if (lane + off < 32) suf_hi += v;
                }
                const unsigned int hi_total = __shfl_sync(0xFFFFFFFFu, suf_hi, 0);

                unsigned int suf_lo = lo;
                #pragma unroll
                for (int off = 1; off < 32; off <<= 1) {
                    const unsigned int v = __shfl_down_sync(0xFFFFFFFFu, suf_lo, off);
                    if (lane + off < 32) suf_lo += v;
                }
                suf_lo += hi_total;

                { const unsigned int st = suf_hi, ab = st - hi;
                  if (st >= krem && ab < krem) {
                      g_prefix[b] = (g_prefix[b] << 16) | (ull)(cbin * 64 + 32 + lane);
                      g_K[b] = (int)(krem - ab);
                  } }
                { const unsigned int st = suf_lo, ab = st - lo;
                  if (st >= krem && ab < krem) {
                      g_prefix[b] = (g_prefix[b] << 16) | (ull)(cbin * 64 + lane);
                      g_K[b] = (int)(krem - ab);
                  } }
            }
            __syncthreads();
        }

        batch_barrier(b, slot++);
    }

    // ---- collect ----
    const ull cutoff = *(volatile ull*)&g_prefix[b];
    #pragma unroll
    for (int j = 0; j < 8; ++j) {
        if (key[j] >= cutoff) {
            const int p = atomicAdd(&g_candcnt[b], 1);
            if (p < Pn) g_cand[b][p] = key[j];
        }
    }

    batch_barrier(b, slot++);   // slot 6

    // ---- restore histograms; sub 0 sorts + emits indices ----
    {
        const int base = sub * 512 + t;
        #pragma unroll
        for (int p = 0; p < 3; ++p) {
            #pragma unroll
            for (int r = 0; r < 8; ++r)
                g_hist[p][b][base + r * 8192] = 0u;
            if (base < 1024) g_coarse[p][b][base] = 0u;
        }
    }
    if (sub == 0) {
        if (t < Pn) skeys[t] = g_cand[b][t];
        __syncthreads();
        for (int kk = 2; kk <= Pn; kk <<= 1) {
            for (int jj = kk >> 1; jj > 0; jj >>= 1) {
                if (t < Pn) {
                    const int ixj = t ^ jj;
                    if (ixj > t) {
                        const ull a = skeys[t];
                        const ull c = skeys[ixj];
                        const bool up = ((t & kk) == 0);
                        if (up ? (a < c) : (a > c)) { skeys[t] = c; skeys[ixj] = a; }
                    }
                }
                __syncthreads();
            }
        }
        if (t < Pn)
            g_idx[b * Pn + t] = (int)(0xFFFFu - (unsigned int)(skeys[t] & 0xFFFFull));
        if (t == 0) {
            g_candcnt[b] = 0;
            g_prefix[b] = 0ull;
            g_K[b] = Pn;
        }
    }

    batch_barrier(b, slot++);   // slot 7: g_idx ready

    // ---- gather: n-rows [sub*16, sub*16+16) ----
    {
        float* F = g_feat + b * Pn * Cn;
        const int n  = sub * 16 + (t >> 5);
        const int d0 = lane * 8;
        const int col = g_idx[b * Pn + n];
        const float* xp = x + (size_t)b * Cn * HWn + col;
        float4 v0, v1;
        v0.x = xp[(size_t)(d0 + 0) * HWn];
        v0.y = xp[(size_t)(d0 + 1) * HWn];
        v0.z = xp[(size_t)(d0 + 2) * HWn];
        v0.w = xp[(size_t)(d0 + 3) * HWn];
        v1.x = xp[(size_t)(d0 + 4) * HWn];
        v1.y = xp[(size_t)(d0 + 5) * HWn];
        v1.z = xp[(size_t)(d0 + 6) * HWn];
        v1.w = xp[(size_t)(d0 + 7) * HWn];
        *(float4*)&F[n * Cn + d0]     = v0;
        *(float4*)&F[n * Cn + d0 + 4] = v1;
    }

    batch_barrier(b, slot++);   // slot 8: F ready

    const int ti = (sub >> 2) * 64;
    const int td = (sub & 3) * 64;
    const int tx = t & 15;
    const int ty = t >> 4;

    // ---- GEMM1 (64x64, KB=32, double-buffered) ----
    {
        const float* F = g_feat + b * Pn * Cn;
        float* Z       = g_z    + b * Pn * Cn;
        const int ai = t >> 3, ak = (t & 7) * 4;
        const int bk = t >> 4, bd = (t & 15) * 4;

        float4 na, nb;
        float acc[2][4] = {};

        na = *(const float4*)&W[(ti + ai) * Pn + ak];
        nb = *(const float4*)&F[bk * Cn + td + bd];
        sA[0][ak + 0][ai] = na.x; sA[0][ak + 1][ai] = na.y;
        sA[0][ak + 2][ai] = na.z; sA[0][ak + 3][ai] = na.w;
        *(float4*)&sB[0][bk][bd] = nb;
        __syncthreads();

        #pragma unroll
        for (int kt = 0; kt < 8; ++kt) {
            const int st = kt & 1;
            if (kt < 7) {
                const int k0 = (kt + 1) * 32;
                na = *(const float4*)&W[(ti + ai) * Pn + k0 + ak];
                nb = *(const float4*)&F[(k0 + bk) * Cn + td + bd];
            }
            #pragma unroll
            for (int k = 0; k < 32; ++k) {
                const float a0 = sA[st][k][ty * 2 + 0];
                const float a1 = sA[st][k][ty * 2 + 1];
                const float4 b4 = *(const float4*)&sB[st][k][tx * 4];
                acc[0][0] += a0 * b4.x; acc[0][1] += a0 * b4.y;
                acc[0][2] += a0 * b4.z; acc[0][3] += a0 * b4.w;
                acc[1][0] += a1 * b4.x; acc[1][1] += a1 * b4.y;
                acc[1][2] += a1 * b4.z; acc[1][3] += a1 * b4.w;
            }
            if (kt < 7) {
                const int sn = st ^ 1;
                sA[sn][ak + 0][ai] = na.x; sA[sn][ak + 1][ai] = na.y;
                sA[sn][ak + 2][ai] = na.z; sA[sn][ak + 3][ai] = na.w;
                *(float4*)&sB[sn][bk][bd] = nb;
            }
            __syncthreads();
        }

        const int d = td + tx * 4;
        #pragma unroll
        for (int ui = 0; ui < 2; ++ui) {
            const int i = ti + ty * 2 + ui;
            const float inv = ga[i] * rsqrtf(va[i] + EPSn);
            const float add = ba[i] - ma[i] * inv;
            const float4 f4 = *(const float4*)&F[i * Cn + d];
            float4 o;
            o.x = fmaxf(acc[ui][0] * inv + add, 0.0f) + f4.x;
            o.y = fmaxf(acc[ui][1] * inv + add, 0.0f) + f4.y;
            o.z = fmaxf(acc[ui][2] * inv + add, 0.0f) + f4.z;
            o.w = fmaxf(acc[ui][3] * inv + add, 0.0f) + f4.w;
            *(float4*)&Z[i * Cn + d] = o;
        }
    }

    batch_barrier(b, slot++);   // slot 9: Z ready

    // ---- GEMM2 (NT, 64x64, KB=32, double-buffered) ----
    {
        const float* Z = g_z  + b * Pn * Cn;
        float* Z2      = g_z2 + b * Pn * Cn;
        const int ar = t >> 3, ak = (t & 7) * 4;

        float4 na, nb;
        float acc[2][4] = {};

        na = *(const float4*)&Z[(ti + ar) * Cn + ak];
        nb = *(const float4*)&Wg[(td + ar) * Cn + ak];
        sA[0][ak + 0][ar] = na.x; sA[0][ak + 1][ar] = na.y;
        sA[0][ak + 2][ar] = na.z; sA[0][ak + 3][ar] = na.w;
        sB[0][ak + 0][ar] = nb.x; sB[0][ak + 1][ar] = nb.y;
        sB[0][ak + 2][ar] = nb.z; sB[0][ak + 3][ar] = nb.w;
        __syncthreads();

        #pragma unroll
        for (int kt = 0; kt < 8; ++kt) {
            const int st = kt & 1;
            if (kt < 7) {
                const int k0 = (kt + 1) * 32;
                na = *(const float4*)&Z[(ti + ar) * Cn + k0 + ak];
                nb = *(const float4*)&Wg[(td + ar) * Cn + k0 + ak];
            }
            #pragma unroll
            for (int k = 0; k < 32; ++k) {
                const float a0 = sA[st][k][ty * 2 + 0];
                const float a1 = sA[st][k][ty * 2 + 1];
                const float4 b4 = *(const float4*)&sB[st][k][tx * 4];
                acc[0][0] += a0 * b4.x; acc[0][1] += a0 * b4.y;
                acc[0][2] += a0 * b4.z; acc[0][3] += a0 * b4.w;
                acc[1][0] += a1 * b4.x; acc[1][1] += a1 * b4.y;
                acc[1][2] += a1 * b4.z; acc[1][3] += a1 * b4.w;
            }
            if (kt < 7) {
                const int sn = st ^ 1;
                sA[sn][ak + 0][ar] = na.x; sA[sn][ak + 1][ar] = na.y;
                sA[sn][ak + 2][ar] = na.z; sA[sn][ak + 3][ar] = na.w;
                sB[sn][ak + 0][ar] = nb.x; sB[sn][ak + 1][ar] = nb.y;
                sB[sn][ak + 2][ar] = nb.z; sB[sn][ak + 3][ar] = nb.w;
            }
            __syncthreads();
        }

        #pragma unroll
        for (int uc = 0; uc < 4; ++uc) {
            const int c = td + tx * 4 + uc;
            const float inv = gw[c] * rsqrtf(vw[c] + EPSn);
            const float add = bw[c] - mw[c] * inv;
            #pragma unroll
            for (int ui = 0; ui < 2; ++ui) {
                const int p = ti + ty * 2 + ui;
                Z2[p * Cn + c] = fmaxf(acc[ui][uc] * inv + add, 0.0f);
            }
        }
    }

    batch_barrier(b, slot++);   // slot 10: z2 fully written (this batch)

    // ---- wait until the whole copy is complete ----
    if (t == 0) {
        while (g_copydone < NCOPY) { }
        __threadfence();
    }
    __syncthreads();

    // ---- scatter: out[b, c, idx[b,p]] = z2[b,p,c] for p in [sub*16, +16) ----
    {
        const float* Z2 = g_z2 + b * Pn * Cn;
        const int p   = sub * 16 + (t >> 5);
        const int col = g_idx[b * Pn + p];
        float* op = out + (size_t)b * Cn * HWn + col;
        #pragma unroll
        for (int k = 0; k < 8; ++k) {
            const int c = lane + k * 32;
            op[(size_t)c * HWn] = Z2[p * Cn + c];
        }
    }

    // ---- last scatterer resets all replay state ----
    __threadfence();
    __syncthreads();
    if (t == 0) {
        const unsigned int r = atomicAdd(&g_scatdone, 1u);
        if (r == NSIDE - 1) {
            *(unsigned int*)&g_copydone = 0u;
            g_scatdone = 0u;
            for (int bb = 0; bb < Bn; ++bb)
                for (int s = 0; s < 12; ++s) g_bar[bb][s] = 0u;
        }
    }
}

// ---------------------------------------------------------------------------
extern "C" void kernel_launch(void* const* d_in, const int* in_sizes, int n_in,
                              void* d_out, int out_size) {
    const float* x     = (const float*)d_in[0];
    const float* edge  = (const float*)d_in[1];
    const float* w_adj = (const float*)d_in[2];
    const float* g_adj = (const float*)d_in[3];
    const float* b_adj = (const float*)d_in[4];
    const float* m_adj = (const float*)d_in[5];
    const float* v_adj = (const float*)d_in[6];
    const float* w_wg  = (const float*)d_in[7];
    const float* g_wg  = (const float*)d_in[8];
    const float* b_wg  = (const float*)d_in[9];
    const float* m_wg  = (const float*)d_in[10];
    const float* v_wg  = (const float*)d_in[11];
    float* out = (float*)d_out;

    // Single launch: role-split CTAs do copy + topk + gather + GEMMs + scatter.
    mega_kernel<<<NTOT, 512>>>((const float4*)x, (float4*)out,
                               x, edge,
                               w_adj, g_adj, b_adj, m_adj, v_adj,
                               w_wg, g_wg, b_wg, m_wg, v_wg,
                               out);
}